// round 1
// baseline (speedup 1.0000x reference)
#include <cuda_runtime.h>
#include <cuda_bf16.h>
#include <math.h>

// Problem constants
#define NTOK 500
#define DM   2048
#define KWIN 10
#define NREL (2*KWIN+1)   // 21

// Scratch (device globals; allocation inside kernel_launch is forbidden)
__device__ float g_Q[NTOK * DM];
__device__ float g_K[NTOK * DM];
__device__ float g_V[NTOK * DM];
__device__ float g_T[NTOK * DM];      // A @ V
__device__ float g_S[NTOK * NTOK];    // scores / attention (in-place)
__device__ float g_QR[NTOK * NREL];

// ---------------------------------------------------------------------------
// Tiled fp32 GEMM, C[M,N] = alpha * A[M,K] @ B[K,N]
// 64x64 block tile, BK=16, 256 threads, 4x4 micro-tile per thread.
// ---------------------------------------------------------------------------
#define BM 64
#define BN 64
#define BK 16
#define TM 4
#define TN 4

__global__ __launch_bounds__(256) void sgemm_nn(
    const float* __restrict__ A, const float* __restrict__ B,
    float* __restrict__ C, int M, int N, int K, float alpha)
{
    __shared__ float As[BK][BM];
    __shared__ float Bs[BK][BN];

    const int bm = blockIdx.y * BM;
    const int bn = blockIdx.x * BN;
    const int tx = threadIdx.x % 16;
    const int ty = threadIdx.x / 16;

    float acc[TM][TN];
#pragma unroll
    for (int i = 0; i < TM; i++)
#pragma unroll
        for (int j = 0; j < TN; j++) acc[i][j] = 0.f;

    for (int k0 = 0; k0 < K; k0 += BK) {
        // Load A tile (BM x BK), store transposed As[k][m]
        for (int t = threadIdx.x; t < BM * BK; t += 256) {
            int r = t / BK, c = t % BK;
            float v = 0.f;
            if (bm + r < M && k0 + c < K) v = A[(size_t)(bm + r) * K + (k0 + c)];
            As[c][r] = v;
        }
        // Load B tile (BK x BN)
        for (int t = threadIdx.x; t < BK * BN; t += 256) {
            int r = t / BN, c = t % BN;
            float v = 0.f;
            if (k0 + r < K && bn + c < N) v = B[(size_t)(k0 + r) * N + (bn + c)];
            Bs[r][c] = v;
        }
        __syncthreads();

#pragma unroll
        for (int kk = 0; kk < BK; ++kk) {
            float a[TM], b[TN];
#pragma unroll
            for (int i = 0; i < TM; i++) a[i] = As[kk][ty * TM + i];
#pragma unroll
            for (int j = 0; j < TN; j++) b[j] = Bs[kk][tx * TN + j];
#pragma unroll
            for (int i = 0; i < TM; i++)
#pragma unroll
                for (int j = 0; j < TN; j++) acc[i][j] += a[i] * b[j];
        }
        __syncthreads();
    }

#pragma unroll
    for (int i = 0; i < TM; i++) {
        int row = bm + ty * TM + i;
        if (row >= M) continue;
#pragma unroll
        for (int j = 0; j < TN; j++) {
            int col = bn + tx * TN + j;
            if (col < N) C[(size_t)row * N + col] = alpha * acc[i][j];
        }
    }
}

// C[M,N] = A[M,K] @ B[N,K]^T   (for S = Qs @ K^T)
__global__ __launch_bounds__(256) void sgemm_nt(
    const float* __restrict__ A, const float* __restrict__ B,
    float* __restrict__ C, int M, int N, int K)
{
    __shared__ float As[BK][BM];
    __shared__ float Bs[BK][BN];

    const int bm = blockIdx.y * BM;
    const int bn = blockIdx.x * BN;
    const int tx = threadIdx.x % 16;
    const int ty = threadIdx.x / 16;

    float acc[TM][TN];
#pragma unroll
    for (int i = 0; i < TM; i++)
#pragma unroll
        for (int j = 0; j < TN; j++) acc[i][j] = 0.f;

    for (int k0 = 0; k0 < K; k0 += BK) {
        for (int t = threadIdx.x; t < BM * BK; t += 256) {
            int r = t / BK, c = t % BK;
            float v = 0.f;
            if (bm + r < M && k0 + c < K) v = A[(size_t)(bm + r) * K + (k0 + c)];
            As[c][r] = v;
        }
        // B tile: Bs[k][n] = B[(bn+n)*K + k0+k]
        for (int t = threadIdx.x; t < BN * BK; t += 256) {
            int r = t / BK, c = t % BK;   // r = n-index, c = k-index
            float v = 0.f;
            if (bn + r < N && k0 + c < K) v = B[(size_t)(bn + r) * K + (k0 + c)];
            Bs[c][r] = v;
        }
        __syncthreads();

#pragma unroll
        for (int kk = 0; kk < BK; ++kk) {
            float a[TM], b[TN];
#pragma unroll
            for (int i = 0; i < TM; i++) a[i] = As[kk][ty * TM + i];
#pragma unroll
            for (int j = 0; j < TN; j++) b[j] = Bs[kk][tx * TN + j];
#pragma unroll
            for (int i = 0; i < TM; i++)
#pragma unroll
                for (int j = 0; j < TN; j++) acc[i][j] += a[i] * b[j];
        }
        __syncthreads();
    }

#pragma unroll
    for (int i = 0; i < TM; i++) {
        int row = bm + ty * TM + i;
        if (row >= M) continue;
#pragma unroll
        for (int j = 0; j < TN; j++) {
            int col = bn + tx * TN + j;
            if (col < N) C[(size_t)row * N + col] = acc[i][j];
        }
    }
}

// QR[i, r] = Qs[i] . wk[r]    (500 x 21, K=2048). One warp per r, one block per i.
__global__ __launch_bounds__(NREL * 32) void qr_kernel(
    const float* __restrict__ Q, const float* __restrict__ wk,
    float* __restrict__ QR)
{
    const int i = blockIdx.x;
    const int warp = threadIdx.x / 32;
    const int lane = threadIdx.x % 32;
    float s = 0.f;
    const float* q = Q + (size_t)i * DM;
    const float* w = wk + (size_t)warp * DM;
    for (int k = lane; k < DM; k += 32) s += q[k] * w[k];
#pragma unroll
    for (int o = 16; o > 0; o >>= 1) s += __shfl_xor_sync(0xffffffffu, s, o);
    if (lane == 0) QR[i * NREL + warp] = s;
}

// Fused: S += relative bias (gather from QR), mask, row softmax.
// One block per row. Writes normalized A in-place into S and into Aout.
__global__ __launch_bounds__(512) void softmax_kernel(
    float* __restrict__ S, const float* __restrict__ QR,
    const int* __restrict__ mask, float* __restrict__ Aout, int n)
{
    const int i = blockIdx.x;
    __shared__ float red[512];
    float* row = S + (size_t)i * n;
    const int* mrow = mask + (size_t)i * n;
    float* arow = Aout + (size_t)i * n;

    // Pass 1: bias + mask, find max
    float m = -INFINITY;
    for (int j = threadIdx.x; j < n; j += blockDim.x) {
        int d = j - i;
        d = min(max(d, -KWIN), KWIN);
        float v = row[j] + QR[i * NREL + d + KWIN];
        if (mrow[j] == 0) v = -1e9f;
        row[j] = v;
        m = fmaxf(m, v);
    }
    red[threadIdx.x] = m;
    __syncthreads();
    for (int s = 256; s > 0; s >>= 1) {
        if (threadIdx.x < s) red[threadIdx.x] = fmaxf(red[threadIdx.x], red[threadIdx.x + s]);
        __syncthreads();
    }
    m = red[0];
    __syncthreads();

    // Pass 2: exp, sum
    float sum = 0.f;
    for (int j = threadIdx.x; j < n; j += blockDim.x) {
        float e = expf(row[j] - m);
        row[j] = e;
        sum += e;
    }
    red[threadIdx.x] = sum;
    __syncthreads();
    for (int s = 256; s > 0; s >>= 1) {
        if (threadIdx.x < s) red[threadIdx.x] += red[threadIdx.x + s];
        __syncthreads();
    }
    const float inv = 1.0f / red[0];
    __syncthreads();

    // Pass 3: normalize, write A (scratch + output)
    for (int j = threadIdx.x; j < n; j += blockDim.x) {
        float a = row[j] * inv;
        row[j] = a;
        arow[j] = a;
    }
}

extern "C" void kernel_launch(void* const* d_in, const int* in_sizes, int n_in,
                              void* d_out, int out_size)
{
    const float* X    = (const float*)d_in[0];   // [500, 2048]
    const int*   mask = (const int*)  d_in[1];   // [500, 500]
    const float* Wq   = (const float*)d_in[2];   // [2048, 2048]
    const float* Wk   = (const float*)d_in[3];
    const float* Wv   = (const float*)d_in[4];
    const float* Wo   = (const float*)d_in[5];
    const float* wk   = (const float*)d_in[6];   // [21, 2048]

    float* Y    = (float*)d_out;                 // [500, 2048]
    float* Aout = Y + (size_t)NTOK * DM;         // [500, 500]

    float* Q  = nullptr; cudaGetSymbolAddress((void**)&Q,  g_Q);
    float* K  = nullptr; cudaGetSymbolAddress((void**)&K,  g_K);
    float* V  = nullptr; cudaGetSymbolAddress((void**)&V,  g_V);
    float* T  = nullptr; cudaGetSymbolAddress((void**)&T,  g_T);
    float* S  = nullptr; cudaGetSymbolAddress((void**)&S,  g_S);
    float* QR = nullptr; cudaGetSymbolAddress((void**)&QR, g_QR);

    const float scale = 1.0f / sqrtf((float)DM);

    dim3 gProj((DM + BN - 1) / BN, (NTOK + BM - 1) / BM);   // 32 x 8
    // Q (pre-scaled), K, V projections
    sgemm_nn<<<gProj, 256>>>(X, Wq, Q, NTOK, DM, DM, scale);
    sgemm_nn<<<gProj, 256>>>(X, Wk, K, NTOK, DM, DM, 1.0f);
    sgemm_nn<<<gProj, 256>>>(X, Wv, V, NTOK, DM, DM, 1.0f);

    // Relative-position projections QR = Qs @ wk^T
    qr_kernel<<<NTOK, NREL * 32>>>(Q, wk, QR);

    // S = Qs @ K^T
    dim3 gS((NTOK + BN - 1) / BN, (NTOK + BM - 1) / BM);    // 8 x 8
    sgemm_nt<<<gS, 256>>>(Q, K, S, NTOK, NTOK, DM);

    // bias + mask + softmax  (A in-place in S, copy to output)
    softmax_kernel<<<NTOK, 512>>>(S, QR, mask, Aout, NTOK);

    // T = A @ V   (K = 500)
    sgemm_nn<<<gProj, 256>>>(S, V, T, NTOK, DM, NTOK, 1.0f);

    // Y = T @ Wo
    sgemm_nn<<<gProj, 256>>>(T, Wo, Y, NTOK, DM, DM, 1.0f);
}

// round 3
// speedup vs baseline: 2.4100x; 2.4100x over previous
#include <cuda_runtime.h>
#include <cuda_bf16.h>
#include <mma.h>
#include <cstdint>
#include <math.h>

using namespace nvcuda;

#define NTOK 500
#define DM   2048
#define KWIN 10
#define NREL (2*KWIN+1)   // 21
#define NQKV (3*DM)       // 6144

// Scratch (device globals; no allocation allowed)
__device__ float g_QKV[NTOK * NQKV];   // [500][6144]: Q | K | V
__device__ float g_T[NTOK * DM];       // A @ V
__device__ float g_S[NTOK * NTOK];     // scores / attention (in-place)
__device__ float g_QR[NTOK * NREL];

__device__ __forceinline__ uint32_t smem_to_u32(const void* p) {
    uint32_t a;
    asm("{ .reg .u64 t; cvta.to.shared.u64 t, %1; cvt.u32.u64 %0, t; }" : "=r"(a) : "l"(p));
    return a;
}
__device__ __forceinline__ void cp16(uint32_t sa, const void* g, bool v) {
    asm volatile("cp.async.ca.shared.global [%0], [%1], 16, %2;"
                 :: "r"(sa), "l"(g), "r"(v ? 16u : 0u) : "memory");
}

// ---------------------------------------------------------------------------
// WMMA tf32 GEMM.  C[M,Ntot] = alpha * A[M,K] @ op(B)
//   MODEB=0: B stored [Ntot][K] row-major  => C = A @ B^T  (S = Q K^T)
//   MODEB=1: B stored [K][2048] row-major, weight section selected by bn>>11
//            from {B0,B1,B2}               => C = A @ B    (projections)
// CTA tile 128x128, Ktile=16, 8 warps (each 32x64 = 2x4 wmma m16n16k8 tiles),
// cp.async double buffering, smem-staged epilogue.
// ---------------------------------------------------------------------------
#define BKT 16
// smem layout (floats): As[2][128*16] at 0, Bs[2][3072] at 4096; C stage overlays at 0.
#define B_STAGE  3072                    // max(16*136, 128*24)
#define SMEM_GEMM (128 * 136 * 4)        // 69632 bytes (C staging dominates)

template<int MODEB>
__device__ __forceinline__ void load_stage(
    float* As, float* Bs, int k0,
    const float* A, const float* Bm,
    int M, int Ntot, int K, int ldA, int ldB,
    int bm, int bn, int bnl, int tid)
{
    // A tile: 128 rows x 16 floats, 512 x 16B chunks
#pragma unroll
    for (int i = 0; i < 2; i++) {
        int ch = tid + 256 * i;
        int r = ch >> 2, cb = ch & 3;
        uint32_t sa = smem_to_u32(As + r * 16 + cb * 4);
        int gr = bm + r, gk = k0 + cb * 4;
        cp16(sa, A + (size_t)gr * ldA + gk, (gr < M) && (gk < K));
    }
    if (MODEB == 1) {
        // B tile: 16 rows x 128 floats (row-major, ld 136)
#pragma unroll
        for (int i = 0; i < 2; i++) {
            int ch = tid + 256 * i;
            int r = ch >> 5, cb = ch & 31;
            uint32_t sa = smem_to_u32(Bs + r * 136 + cb * 4);
            int gk = k0 + r;
            cp16(sa, Bm + (size_t)gk * ldB + bnl + cb * 4, gk < K);
        }
    } else {
        // B tile: 128 n-rows x 16 k-floats (row-major, ld 24)
#pragma unroll
        for (int i = 0; i < 2; i++) {
            int ch = tid + 256 * i;
            int r = ch >> 2, cb = ch & 3;
            uint32_t sa = smem_to_u32(Bs + r * 24 + cb * 4);
            int gn = bn + r, gk = k0 + cb * 4;
            cp16(sa, Bm + (size_t)gn * ldB + gk, (gn < Ntot) && (gk < K));
        }
    }
}

template<int MODEB>
__global__ __launch_bounds__(256, 1) void wmma_gemm(
    const float* __restrict__ A,
    const float* __restrict__ B0, const float* __restrict__ B1, const float* __restrict__ B2,
    float* __restrict__ C,
    int M, int Ntot, int K, int ldA, int ldB, int ldC, float alpha)
{
    extern __shared__ float smem[];
    float* AsBase = smem;                 // 2 x 2048
    float* BsBase = smem + 4096;          // 2 x 3072
    float* Cst    = smem;                 // overlays (used after main loop)

    const int tid = threadIdx.x;
    const int w = tid >> 5;
    const int warpM = w & 3;              // 4 warps along M (32 rows each)
    const int warpN = w >> 2;             // 2 warps along N (64 cols each)
    const int bm = blockIdx.y * 128, bn = blockIdx.x * 128;

    const float* Bm;
    int bnl;
    if (MODEB == 1) {
        int sel = bn >> 11;
        Bm = (sel == 0) ? B0 : ((sel == 1) ? B1 : B2);
        bnl = bn & 2047;
    } else { Bm = B0; bnl = bn; }

    wmma::fragment<wmma::accumulator, 16, 16, 8, float> acc[2][4];
#pragma unroll
    for (int i = 0; i < 2; i++)
#pragma unroll
        for (int j = 0; j < 4; j++) wmma::fill_fragment(acc[i][j], 0.0f);

    const int nStages = (K + BKT - 1) / BKT;

    load_stage<MODEB>(AsBase, BsBase, 0, A, Bm, M, Ntot, K, ldA, ldB, bm, bn, bnl, tid);
    asm volatile("cp.async.commit_group;" ::: "memory");

    for (int s = 0; s < nStages; ++s) {
        const int b = s & 1;
        if (s + 1 < nStages) {
            load_stage<MODEB>(AsBase + ((s + 1) & 1) * 2048, BsBase + ((s + 1) & 1) * B_STAGE,
                              (s + 1) * BKT, A, Bm, M, Ntot, K, ldA, ldB, bm, bn, bnl, tid);
            asm volatile("cp.async.commit_group;" ::: "memory");
            asm volatile("cp.async.wait_group 1;" ::: "memory");
        } else {
            asm volatile("cp.async.wait_group 0;" ::: "memory");
        }
        __syncthreads();

        float* As = AsBase + b * 2048;
        float* Bs = BsBase + b * B_STAGE;
#pragma unroll
        for (int kk = 0; kk < 2; kk++) {
            wmma::fragment<wmma::matrix_a, 16, 16, 8, wmma::precision::tf32, wmma::row_major> af[2];
#pragma unroll
            for (int i = 0; i < 2; i++) {
                wmma::load_matrix_sync(af[i], As + (warpM * 32 + i * 16) * 16 + kk * 8, 16);
#pragma unroll
                for (int t = 0; t < af[i].num_elements; t++)
                    af[i].x[t] = wmma::__float_to_tf32(af[i].x[t]);
            }
            if (MODEB == 1) {
                wmma::fragment<wmma::matrix_b, 16, 16, 8, wmma::precision::tf32, wmma::row_major> bf;
#pragma unroll
                for (int j = 0; j < 4; j++) {
                    wmma::load_matrix_sync(bf, Bs + kk * 8 * 136 + warpN * 64 + j * 16, 136);
#pragma unroll
                    for (int t = 0; t < bf.num_elements; t++)
                        bf.x[t] = wmma::__float_to_tf32(bf.x[t]);
#pragma unroll
                    for (int i = 0; i < 2; i++)
                        wmma::mma_sync(acc[i][j], af[i], bf, acc[i][j]);
                }
            } else {
                wmma::fragment<wmma::matrix_b, 16, 16, 8, wmma::precision::tf32, wmma::col_major> bf;
#pragma unroll
                for (int j = 0; j < 4; j++) {
                    wmma::load_matrix_sync(bf, Bs + (warpN * 64 + j * 16) * 24 + kk * 8, 24);
#pragma unroll
                    for (int t = 0; t < bf.num_elements; t++)
                        bf.x[t] = wmma::__float_to_tf32(bf.x[t]);
#pragma unroll
                    for (int i = 0; i < 2; i++)
                        wmma::mma_sync(acc[i][j], af[i], bf, acc[i][j]);
                }
            }
        }
        __syncthreads();
    }

    // Epilogue: stage to smem, then guarded vectorized copy with alpha
#pragma unroll
    for (int i = 0; i < 2; i++)
#pragma unroll
        for (int j = 0; j < 4; j++)
            wmma::store_matrix_sync(Cst + (warpM * 32 + i * 16) * 136 + warpN * 64 + j * 16,
                                    acc[i][j], 136, wmma::mem_row_major);
    __syncthreads();

    for (int idx = tid; idx < 128 * 32; idx += 256) {
        int r = idx >> 5, c4 = idx & 31;
        int row = bm + r, col = bn + c4 * 4;
        if (row < M && col < Ntot) {
            float4 v = *(float4*)(Cst + r * 136 + c4 * 4);
            v.x *= alpha; v.y *= alpha; v.z *= alpha; v.w *= alpha;
            *(float4*)(C + (size_t)row * ldC + col) = v;
        }
    }
}

// ---------------------------------------------------------------------------
// QR[i, r] = scale * (Q[i] . wk[r]).  wk cached in smem; 25 blocks x 20 rows.
// ---------------------------------------------------------------------------
#define QR_BLOCKS 25
#define QR_ROWS   20
#define QR_THREADS (NREL * 32)  // 672
#define QR_SMEM ((NREL * DM + DM) * 4)

__global__ __launch_bounds__(QR_THREADS, 1) void qr_kernel(
    const float* __restrict__ Q, int ldQ, const float* __restrict__ wk,
    float* __restrict__ QR, float scale)
{
    extern __shared__ float qsm[];
    float* wks = qsm;             // [21*2048]
    float* qv  = qsm + NREL * DM; // [2048]
    const int tid = threadIdx.x, warp = tid / 32, lane = tid & 31;

    for (int t = tid; t < NREL * DM; t += QR_THREADS) wks[t] = wk[t];
    __syncthreads();

    for (int ii = 0; ii < QR_ROWS; ii++) {
        const int i = blockIdx.x * QR_ROWS + ii;
        for (int t = tid; t < DM; t += QR_THREADS) qv[t] = Q[(size_t)i * ldQ + t];
        __syncthreads();
        if (warp < NREL) {
            float s = 0.f;
            const float* wp = wks + warp * DM;
#pragma unroll 4
            for (int k = lane; k < DM; k += 32) s += qv[k] * wp[k];
#pragma unroll
            for (int o = 16; o > 0; o >>= 1) s += __shfl_xor_sync(0xffffffffu, s, o);
            if (lane == 0) QR[i * NREL + warp] = s * scale;
        }
        __syncthreads();
    }
}

// ---------------------------------------------------------------------------
// Fused bias + mask + softmax.  In-place on S; also writes Aout.
// ---------------------------------------------------------------------------
__global__ __launch_bounds__(512) void softmax_kernel(
    float* __restrict__ S, const float* __restrict__ QR,
    const int* __restrict__ mask, float* __restrict__ Aout, int n)
{
    const int i = blockIdx.x;
    __shared__ float red[512];
    float* row = S + (size_t)i * n;
    const int* mrow = mask + (size_t)i * n;
    float* arow = Aout + (size_t)i * n;

    float m = -INFINITY;
    for (int j = threadIdx.x; j < n; j += blockDim.x) {
        int d = j - i;
        d = min(max(d, -KWIN), KWIN);
        float v = row[j] + QR[i * NREL + d + KWIN];
        if (mrow[j] == 0) v = -1e9f;
        row[j] = v;
        m = fmaxf(m, v);
    }
    red[threadIdx.x] = m;
    __syncthreads();
    for (int s = 256; s > 0; s >>= 1) {
        if (threadIdx.x < s) red[threadIdx.x] = fmaxf(red[threadIdx.x], red[threadIdx.x + s]);
        __syncthreads();
    }
    m = red[0];
    __syncthreads();

    float sum = 0.f;
    for (int j = threadIdx.x; j < n; j += blockDim.x) {
        float e = expf(row[j] - m);
        row[j] = e;
        sum += e;
    }
    red[threadIdx.x] = sum;
    __syncthreads();
    for (int s = 256; s > 0; s >>= 1) {
        if (threadIdx.x < s) red[threadIdx.x] += red[threadIdx.x + s];
        __syncthreads();
    }
    const float inv = 1.0f / red[0];
    __syncthreads();

    for (int j = threadIdx.x; j < n; j += blockDim.x) {
        float a = row[j] * inv;
        row[j] = a;
        arow[j] = a;
    }
}

// ---------------------------------------------------------------------------
extern "C" void kernel_launch(void* const* d_in, const int* in_sizes, int n_in,
                              void* d_out, int out_size)
{
    const float* X    = (const float*)d_in[0];   // [500, 2048]
    const int*   mask = (const int*)  d_in[1];   // [500, 500]
    const float* Wq   = (const float*)d_in[2];   // [2048, 2048]
    const float* Wk   = (const float*)d_in[3];
    const float* Wv   = (const float*)d_in[4];
    const float* Wo   = (const float*)d_in[5];
    const float* wk   = (const float*)d_in[6];   // [21, 2048]

    float* Y    = (float*)d_out;                 // [500, 2048]
    float* Aout = Y + (size_t)NTOK * DM;         // [500, 500]

    float* QKV = nullptr; cudaGetSymbolAddress((void**)&QKV, g_QKV);
    float* T   = nullptr; cudaGetSymbolAddress((void**)&T,   g_T);
    float* S   = nullptr; cudaGetSymbolAddress((void**)&S,   g_S);
    float* QR  = nullptr; cudaGetSymbolAddress((void**)&QR,  g_QR);

    cudaFuncSetAttribute(wmma_gemm<0>, cudaFuncAttributeMaxDynamicSharedMemorySize, SMEM_GEMM);
    cudaFuncSetAttribute(wmma_gemm<1>, cudaFuncAttributeMaxDynamicSharedMemorySize, SMEM_GEMM);
    cudaFuncSetAttribute(qr_kernel, cudaFuncAttributeMaxDynamicSharedMemorySize, QR_SMEM);

    const float scale = 1.0f / sqrtf((float)DM);
    float* Qp = QKV;            // ld 6144
    float* Kp = QKV + DM;
    float* Vp = QKV + 2 * DM;

    // 1) Fused QKV projection: [500,6144] = X @ [Wq|Wk|Wv]
    wmma_gemm<1><<<dim3(NQKV / 128, 4), 256, SMEM_GEMM>>>(
        X, Wq, Wk, Wv, QKV, NTOK, NQKV, DM, DM, DM, NQKV, 1.0f);

    // 2) QR = scale * Q @ wk^T
    qr_kernel<<<QR_BLOCKS, QR_THREADS, QR_SMEM>>>(Qp, NQKV, wk, QR, scale);

    // 3) S = scale * Q @ K^T
    wmma_gemm<0><<<dim3(4, 4), 256, SMEM_GEMM>>>(
        Qp, Kp, Kp, Kp, S, NTOK, NTOK, DM, NQKV, NQKV, NTOK, scale);

    // 4) bias + mask + softmax (A in place, copy to output)
    softmax_kernel<<<NTOK, 512>>>(S, QR, mask, Aout, NTOK);

    // 5) T = A @ V
    wmma_gemm<1><<<dim3(16, 4), 256, SMEM_GEMM>>>(
        S, Vp, Vp, Vp, T, NTOK, DM, NTOK, NTOK, NQKV, DM, 1.0f);

    // 6) Y = T @ Wo
    wmma_gemm<1><<<dim3(16, 4), 256, SMEM_GEMM>>>(
        T, Wo, Wo, Wo, Y, NTOK, DM, DM, DM, DM, DM, 1.0f);
}

// round 4
// speedup vs baseline: 7.9793x; 3.3110x over previous
#include <cuda_runtime.h>
#include <cuda_fp16.h>
#include <cstdint>
#include <math.h>

#define NTOK  500
#define NTOKP 512
#define DM    2048
#define KWIN  10
#define NREL  21
#define NQKV  6144

// ---------------- scratch (device globals; no allocation allowed) ----------
__device__ __align__(16) __half g_X16 [NTOK * DM];
__device__ __align__(16) __half g_W16 [DM * NQKV];     // [k][Wq|Wk|Wv]
__device__ __align__(16) __half g_Wo16[DM * DM];
__device__ __align__(16) __half g_QKV16[NTOK * NQKV];  // [tok][Q|K|V]
__device__ __align__(16) __half g_A16 [NTOK * NTOKP];  // attention, zero-padded cols
__device__ __align__(16) __half g_T16 [NTOK * DM];
__device__ float g_S [NTOK * NTOK];
__device__ float g_QR[NTOK * NREL];

// ---------------- PTX helpers ----------------------------------------------
__device__ __forceinline__ uint32_t smem_to_u32(const void* p) {
    uint32_t a;
    asm("{ .reg .u64 t; cvta.to.shared.u64 t, %1; cvt.u32.u64 %0, t; }" : "=r"(a) : "l"(p));
    return a;
}
__device__ __forceinline__ void cp16(uint32_t sa, const void* g, bool v) {
    asm volatile("cp.async.ca.shared.global [%0], [%1], 16, %2;"
                 :: "r"(sa), "l"(g), "r"(v ? 16u : 0u) : "memory");
}
__device__ __forceinline__ void ldsm4(uint32_t& r0, uint32_t& r1, uint32_t& r2, uint32_t& r3,
                                      uint32_t addr) {
    asm volatile("ldmatrix.sync.aligned.m8n8.x4.shared.b16 {%0,%1,%2,%3}, [%4];"
                 : "=r"(r0), "=r"(r1), "=r"(r2), "=r"(r3) : "r"(addr));
}
__device__ __forceinline__ void ldsm4t(uint32_t& r0, uint32_t& r1, uint32_t& r2, uint32_t& r3,
                                       uint32_t addr) {
    asm volatile("ldmatrix.sync.aligned.m8n8.x4.trans.shared.b16 {%0,%1,%2,%3}, [%4];"
                 : "=r"(r0), "=r"(r1), "=r"(r2), "=r"(r3) : "r"(addr));
}
__device__ __forceinline__ void mma16816(float* c, const uint32_t* a, uint32_t b0, uint32_t b1) {
    asm volatile("mma.sync.aligned.m16n8k16.row.col.f32.f16.f16.f32 "
                 "{%0,%1,%2,%3}, {%4,%5,%6,%7}, {%8,%9}, {%0,%1,%2,%3};"
                 : "+f"(c[0]), "+f"(c[1]), "+f"(c[2]), "+f"(c[3])
                 : "r"(a[0]), "r"(a[1]), "r"(a[2]), "r"(a[3]), "r"(b0), "r"(b1));
}

// ---------------------------------------------------------------------------
// fp16 GEMM, fp32 accumulate.  C = alpha * A[M,K] @ op(B)
//   MODEB=0: B [N][K] row-major (fp16)      => C = A @ B^T   (S = Q K^T)
//   MODEB=1: B [K][N] row-major (fp16)      => C = A @ B     (weights / V)
// CTA 128x128, BK=32, 8 warps (2 along M x 4 along N), 3-stage cp.async,
// ldmatrix (+.trans for MODEB=1), mma.m16n8k16.
// ---------------------------------------------------------------------------
#define BK 32
#define SA  40      // halves: 32 + 8 pad (A tile and mode0 B tile)
#define SB1 136     // halves: 128 + 8 pad (mode1 B tile)
#define A_BYTES  (128 * SA * 2)     // 10240
#define B0_BYTES (128 * SA * 2)     // 10240
#define B1_BYTES (32 * SB1 * 2)     // 8704
#define NSTAGE 3

template<int MODEB>
__global__ __launch_bounds__(256, 1) void hgemm(
    const __half* __restrict__ A, const __half* __restrict__ B,
    float* __restrict__ C32, __half* __restrict__ C16,
    int M, int N, int K, int KB,
    int ldA, int ldB, int ldC32, int ldC16, float alpha)
{
    extern __shared__ char smem[];
    const uint32_t sb = smem_to_u32(smem);
    constexpr int BB  = MODEB ? B1_BYTES : B0_BYTES;
    constexpr int STG = A_BYTES + BB;

    const int tid = threadIdx.x;
    const int lane = tid & 31, w = tid >> 5;
    const int wm = w & 1, wn = w >> 1;                // 2 x 4 warp grid
    const int bm = blockIdx.y * 128, bn = blockIdx.x * 128;
    const int nIter = K / BK;

    float acc[4][4][4];
#pragma unroll
    for (int i = 0; i < 4; i++)
#pragma unroll
        for (int j = 0; j < 4; j++)
#pragma unroll
            for (int t = 0; t < 4; t++) acc[i][j][t] = 0.f;

    // ---- stage loader --------------------------------------------------
    auto load = [&](int s, int buf) {
        const int k0 = s * BK;
        const uint32_t aS = sb + (uint32_t)buf * STG;
        const uint32_t bS = aS + A_BYTES;
#pragma unroll
        for (int i = 0; i < 2; i++) {                 // A: 128 rows x 64B
            int ch = tid + 256 * i;
            int r = ch >> 2, cb = ch & 3;
            uint32_t sa = aS + (r * SA + cb * 8) * 2;
            int gr = bm + r;
            cp16(sa, A + (size_t)gr * ldA + k0 + cb * 8, gr < M);
        }
        if (MODEB) {
#pragma unroll
            for (int i = 0; i < 2; i++) {             // B: 32 k-rows x 256B
                int ch = tid + 256 * i;
                int r = ch >> 4, cb = ch & 15;
                uint32_t sa = bS + (r * SB1 + cb * 8) * 2;
                int gk = k0 + r;
                cp16(sa, B + (size_t)gk * ldB + bn + cb * 8, gk < KB);
            }
        } else {
#pragma unroll
            for (int i = 0; i < 2; i++) {             // B: 128 n-rows x 64B
                int ch = tid + 256 * i;
                int r = ch >> 2, cb = ch & 3;
                uint32_t sa = bS + (r * SA + cb * 8) * 2;
                int gn = bn + r;
                cp16(sa, B + (size_t)gn * ldB + k0 + cb * 8, gn < N);
            }
        }
        asm volatile("cp.async.commit_group;" ::: "memory");
    };

    load(0, 0);
    load(1, 1);

    // per-lane ldmatrix offsets
    const int arow  = lane & 15;
    const int acol  = (lane >> 4) * 8;
    const int b0row = (lane & 7) + ((lane >> 4) & 1) * 8;   // mode0 (no trans)
    const int b0col = ((lane >> 3) & 1) * 8;
    const int b1row = (lane & 7) + ((lane >> 3) & 1) * 8;   // mode1 (.trans)
    const int b1col = ((lane >> 4) & 1) * 8;

    for (int it = 0; it < nIter; ++it) {
        asm volatile("cp.async.wait_group 1;" ::: "memory");
        __syncthreads();
        const uint32_t aS = sb + (uint32_t)(it % NSTAGE) * STG;
        const uint32_t bS = aS + A_BYTES;

#pragma unroll
        for (int kk = 0; kk < 2; kk++) {
            uint32_t a[4][4];
#pragma unroll
            for (int mi = 0; mi < 4; mi++) {
                uint32_t addr = aS + (uint32_t)(((wm * 64 + mi * 16 + arow) * SA) + kk * 16 + acol) * 2;
                ldsm4(a[mi][0], a[mi][1], a[mi][2], a[mi][3], addr);
            }
            uint32_t b[2][4];
#pragma unroll
            for (int nb = 0; nb < 2; nb++) {
                if (MODEB) {
                    uint32_t addr = bS + (uint32_t)(((kk * 16 + b1row) * SB1) + wn * 32 + nb * 16 + b1col) * 2;
                    ldsm4t(b[nb][0], b[nb][1], b[nb][2], b[nb][3], addr);
                } else {
                    uint32_t addr = bS + (uint32_t)(((wn * 32 + nb * 16 + b0row) * SA) + kk * 16 + b0col) * 2;
                    ldsm4(b[nb][0], b[nb][1], b[nb][2], b[nb][3], addr);
                }
            }
#pragma unroll
            for (int mi = 0; mi < 4; mi++)
#pragma unroll
                for (int nj = 0; nj < 4; nj++)
                    mma16816(acc[mi][nj], a[mi],
                             b[nj >> 1][2 * (nj & 1)], b[nj >> 1][2 * (nj & 1) + 1]);
        }
        if (it + 2 < nIter) load(it + 2, (it + 2) % NSTAGE);
        else asm volatile("cp.async.commit_group;" ::: "memory");
    }

    // ---- epilogue: direct register stores ------------------------------
#pragma unroll
    for (int mi = 0; mi < 4; mi++) {
        const int r0 = bm + wm * 64 + mi * 16 + (lane >> 2);
#pragma unroll
        for (int nj = 0; nj < 4; nj++) {
            const int c0 = bn + wn * 32 + nj * 8 + 2 * (lane & 3);
            const float* ac = acc[mi][nj];
            if (C32) {
                if (r0 < M && c0 < N)
                    *(float2*)(C32 + (size_t)r0 * ldC32 + c0) =
                        make_float2(ac[0] * alpha, ac[1] * alpha);
                if (r0 + 8 < M && c0 < N)
                    *(float2*)(C32 + (size_t)(r0 + 8) * ldC32 + c0) =
                        make_float2(ac[2] * alpha, ac[3] * alpha);
            }
            if (C16) {
                if (r0 < M && c0 < N)
                    *(__half2*)(C16 + (size_t)r0 * ldC16 + c0) =
                        __floats2half2_rn(ac[0] * alpha, ac[1] * alpha);
                if (r0 + 8 < M && c0 < N)
                    *(__half2*)(C16 + (size_t)(r0 + 8) * ldC16 + c0) =
                        __floats2half2_rn(ac[2] * alpha, ac[3] * alpha);
            }
        }
    }
}

// ---------------------------------------------------------------------------
// fp32 -> fp16 conversion kernels
// ---------------------------------------------------------------------------
__global__ void cvt1(const float4* __restrict__ s, __half2* __restrict__ d, int n4) {
    int i = blockIdx.x * blockDim.x + threadIdx.x;
    if (i < n4) {
        float4 v = s[i];
        d[2 * i]     = __floats2half2_rn(v.x, v.y);
        d[2 * i + 1] = __floats2half2_rn(v.z, v.w);
    }
}
// Fuse Wq|Wk|Wv into [k][6144] fp16
__global__ void cvt_fuse3(const float4* __restrict__ q, const float4* __restrict__ k,
                          const float4* __restrict__ v, __half* __restrict__ d) {
    int i = blockIdx.x * blockDim.x + threadIdx.x;     // over 2048*2048/4
    if (i < DM * DM / 4) {
        int p = i * 4;
        int row = p >> 11, col = p & 2047;
        float4 a;
        __half2* dq = (__half2*)(d + (size_t)row * NQKV + col);
        a = q[i]; dq[0] = __floats2half2_rn(a.x, a.y); dq[1] = __floats2half2_rn(a.z, a.w);
        __half2* dk = (__half2*)(d + (size_t)row * NQKV + 2048 + col);
        a = k[i]; dk[0] = __floats2half2_rn(a.x, a.y); dk[1] = __floats2half2_rn(a.z, a.w);
        __half2* dv = (__half2*)(d + (size_t)row * NQKV + 4096 + col);
        a = v[i]; dv[0] = __floats2half2_rn(a.x, a.y); dv[1] = __floats2half2_rn(a.z, a.w);
    }
}

// ---------------------------------------------------------------------------
// QR[i, r] = scale * (Q[i] . wk[r]).  wk cached in smem; Q fp16.
// ---------------------------------------------------------------------------
#define QR_BLOCKS 25
#define QR_ROWS   20
#define QR_THREADS (NREL * 32)  // 672
#define QR_SMEM ((NREL * DM + DM) * 4)

__global__ __launch_bounds__(QR_THREADS, 1) void qr_kernel(
    const __half* __restrict__ Q, int ldQ, const float* __restrict__ wk,
    float* __restrict__ QR, float scale)
{
    extern __shared__ float qsm[];
    float* wks = qsm;             // [21*2048]
    float* qv  = qsm + NREL * DM; // [2048]
    const int tid = threadIdx.x, warp = tid / 32, lane = tid & 31;

    for (int t = tid; t < NREL * DM; t += QR_THREADS) wks[t] = wk[t];
    __syncthreads();

    for (int ii = 0; ii < QR_ROWS; ii++) {
        const int i = blockIdx.x * QR_ROWS + ii;
        for (int t = tid; t < DM; t += QR_THREADS)
            qv[t] = __half2float(Q[(size_t)i * ldQ + t]);
        __syncthreads();
        if (warp < NREL) {
            float s = 0.f;
            const float* wp = wks + warp * DM;
#pragma unroll 4
            for (int k = lane; k < DM; k += 32) s += qv[k] * wp[k];
#pragma unroll
            for (int o = 16; o > 0; o >>= 1) s += __shfl_xor_sync(0xffffffffu, s, o);
            if (lane == 0) QR[i * NREL + warp] = s * scale;
        }
        __syncthreads();
    }
}

// ---------------------------------------------------------------------------
// Fused bias + mask + softmax.  Reads fp32 S; writes fp32 Aout and fp16 A16.
// ---------------------------------------------------------------------------
__global__ __launch_bounds__(512) void softmax_kernel(
    float* __restrict__ S, const float* __restrict__ QR,
    const int* __restrict__ mask, float* __restrict__ Aout,
    __half* __restrict__ A16, int n)
{
    const int i = blockIdx.x;
    __shared__ float red[512];
    float* row = S + (size_t)i * n;
    const int* mrow = mask + (size_t)i * n;
    float* arow = Aout + (size_t)i * n;
    __half* hrow = A16 + (size_t)i * NTOKP;

    float m = -INFINITY;
    for (int j = threadIdx.x; j < n; j += blockDim.x) {
        int d = j - i;
        d = min(max(d, -KWIN), KWIN);
        float v = row[j] + QR[i * NREL + d + KWIN];
        if (mrow[j] == 0) v = -1e9f;
        row[j] = v;
        m = fmaxf(m, v);
    }
    red[threadIdx.x] = m;
    __syncthreads();
    for (int s = 256; s > 0; s >>= 1) {
        if (threadIdx.x < s) red[threadIdx.x] = fmaxf(red[threadIdx.x], red[threadIdx.x + s]);
        __syncthreads();
    }
    m = red[0];
    __syncthreads();

    float sum = 0.f;
    for (int j = threadIdx.x; j < n; j += blockDim.x) {
        float e = expf(row[j] - m);
        row[j] = e;
        sum += e;
    }
    red[threadIdx.x] = sum;
    __syncthreads();
    for (int s = 256; s > 0; s >>= 1) {
        if (threadIdx.x < s) red[threadIdx.x] += red[threadIdx.x + s];
        __syncthreads();
    }
    const float inv = 1.0f / red[0];
    __syncthreads();

    for (int j = threadIdx.x; j < n; j += blockDim.x) {
        float a = row[j] * inv;
        arow[j] = a;
        hrow[j] = __float2half_rn(a);
    }
    for (int j = n + threadIdx.x; j < NTOKP; j += blockDim.x) hrow[j] = __float2half_rn(0.f);
}

// ---------------------------------------------------------------------------
extern "C" void kernel_launch(void* const* d_in, const int* in_sizes, int n_in,
                              void* d_out, int out_size)
{
    const float* X    = (const float*)d_in[0];   // [500, 2048]
    const int*   mask = (const int*)  d_in[1];   // [500, 500]
    const float* Wq   = (const float*)d_in[2];   // [2048, 2048]
    const float* Wk   = (const float*)d_in[3];
    const float* Wv   = (const float*)d_in[4];
    const float* Wo   = (const float*)d_in[5];
    const float* wk   = (const float*)d_in[6];   // [21, 2048]

    float* Y    = (float*)d_out;                 // [500, 2048]
    float* Aout = Y + (size_t)NTOK * DM;         // [500, 500]

    __half *X16, *W16, *Wo16, *QKV16, *A16, *T16;
    float *S, *QR;
    cudaGetSymbolAddress((void**)&X16,   g_X16);
    cudaGetSymbolAddress((void**)&W16,   g_W16);
    cudaGetSymbolAddress((void**)&Wo16,  g_Wo16);
    cudaGetSymbolAddress((void**)&QKV16, g_QKV16);
    cudaGetSymbolAddress((void**)&A16,   g_A16);
    cudaGetSymbolAddress((void**)&T16,   g_T16);
    cudaGetSymbolAddress((void**)&S,     g_S);
    cudaGetSymbolAddress((void**)&QR,    g_QR);

    const int SM0 = NSTAGE * (A_BYTES + B0_BYTES);   // 61440
    const int SM1 = NSTAGE * (A_BYTES + B1_BYTES);   // 56832
    cudaFuncSetAttribute(hgemm<0>, cudaFuncAttributeMaxDynamicSharedMemorySize, SM0);
    cudaFuncSetAttribute(hgemm<1>, cudaFuncAttributeMaxDynamicSharedMemorySize, SM1);
    cudaFuncSetAttribute(qr_kernel, cudaFuncAttributeMaxDynamicSharedMemorySize, QR_SMEM);

    const float scale = 1.0f / sqrtf((float)DM);

    // 0) fp32 -> fp16 conversions
    cvt1<<<(NTOK * DM / 4 + 255) / 256, 256>>>((const float4*)X, (__half2*)X16, NTOK * DM / 4);
    cvt_fuse3<<<(DM * DM / 4 + 255) / 256, 256>>>(
        (const float4*)Wq, (const float4*)Wk, (const float4*)Wv, W16);
    cvt1<<<(DM * DM / 4 + 255) / 256, 256>>>((const float4*)Wo, (__half2*)Wo16, DM * DM / 4);

    // 1) QKV = X @ [Wq|Wk|Wv]   (fp16 out)
    hgemm<1><<<dim3(NQKV / 128, 4), 256, SM1>>>(
        X16, W16, nullptr, QKV16, NTOK, NQKV, DM, DM, DM, NQKV, 0, NQKV, 1.0f);

    // 2) QR = scale * Q @ wk^T
    qr_kernel<<<QR_BLOCKS, QR_THREADS, QR_SMEM>>>(QKV16, NQKV, wk, QR, scale);

    // 3) S = scale * Q @ K^T    (fp32 out)
    hgemm<0><<<dim3(4, 4), 256, SM0>>>(
        QKV16, QKV16 + DM, S, nullptr, NTOK, NTOK, DM, DM, NQKV, NQKV, NTOK, 0, scale);

    // 4) bias + mask + softmax  (fp32 Aout + fp16 A16)
    softmax_kernel<<<NTOK, 512>>>(S, QR, mask, Aout, A16, NTOK);

    // 5) T = A @ V              (K padded to 512; V rows >=500 zero-filled)
    hgemm<1><<<dim3(DM / 128, 4), 256, SM1>>>(
        A16, QKV16 + 2 * DM, nullptr, T16, NTOK, DM, NTOKP, NTOK, NTOKP, NQKV, 0, DM, 1.0f);

    // 6) Y = T @ Wo             (fp32 out)
    hgemm<1><<<dim3(DM / 128, 4), 256, SM1>>>(
        T16, Wo16, Y, nullptr, NTOK, DM, DM, DM, DM, DM, DM, 0, 1.0f);
}

// round 5
// speedup vs baseline: 9.4764x; 1.1876x over previous
#include <cuda_runtime.h>
#include <cuda_fp16.h>
#include <cstdint>
#include <math.h>

#define NTOK  500
#define NTOKP 512
#define DM    2048
#define KWIN  10
#define NREL  21
#define NQKV  6144

// ---------------- scratch (device globals; no allocation allowed) ----------
__device__ __align__(16) __half g_X16 [NTOK * DM];
__device__ __align__(16) __half g_W16 [DM * NQKV];     // [k][Wq|Wk|Wv]
__device__ __align__(16) __half g_Wo16[DM * DM];
__device__ __align__(16) __half g_QKV16[NTOK * NQKV];  // [tok][Q|K|V]
__device__ __align__(16) __half g_A16 [NTOK * NTOKP];  // attention, zero-padded cols
__device__ __align__(16) __half g_T16 [NTOK * DM];
__device__ float g_S [NTOK * NTOK];
__device__ float g_QR[NTOK * NREL];

// ---------------- PTX helpers ----------------------------------------------
__device__ __forceinline__ uint32_t smem_to_u32(const void* p) {
    uint32_t a;
    asm("{ .reg .u64 t; cvta.to.shared.u64 t, %1; cvt.u32.u64 %0, t; }" : "=r"(a) : "l"(p));
    return a;
}
__device__ __forceinline__ void cp16(uint32_t sa, const void* g, bool v) {
    asm volatile("cp.async.ca.shared.global [%0], [%1], 16, %2;"
                 :: "r"(sa), "l"(g), "r"(v ? 16u : 0u) : "memory");
}
__device__ __forceinline__ void ldsm4(uint32_t& r0, uint32_t& r1, uint32_t& r2, uint32_t& r3,
                                      uint32_t addr) {
    asm volatile("ldmatrix.sync.aligned.m8n8.x4.shared.b16 {%0,%1,%2,%3}, [%4];"
                 : "=r"(r0), "=r"(r1), "=r"(r2), "=r"(r3) : "r"(addr));
}
__device__ __forceinline__ void ldsm4t(uint32_t& r0, uint32_t& r1, uint32_t& r2, uint32_t& r3,
                                       uint32_t addr) {
    asm volatile("ldmatrix.sync.aligned.m8n8.x4.trans.shared.b16 {%0,%1,%2,%3}, [%4];"
                 : "=r"(r0), "=r"(r1), "=r"(r2), "=r"(r3) : "r"(addr));
}
__device__ __forceinline__ void mma16816(float* c, const uint32_t* a, uint32_t b0, uint32_t b1) {
    asm volatile("mma.sync.aligned.m16n8k16.row.col.f32.f16.f16.f32 "
                 "{%0,%1,%2,%3}, {%4,%5,%6,%7}, {%8,%9}, {%0,%1,%2,%3};"
                 : "+f"(c[0]), "+f"(c[1]), "+f"(c[2]), "+f"(c[3])
                 : "r"(a[0]), "r"(a[1]), "r"(a[2]), "r"(a[3]), "r"(b0), "r"(b1));
}

// ---------------------------------------------------------------------------
// fp16 GEMM, fp32 accumulate.  C = alpha * A[M,K] @ op(B)
//   MODEB=0: B [N][K] row-major => C = A @ B^T   (S = Q K^T)
//   MODEB=1: B [K][N] row-major => C = A @ B     (weights / V)
// CTA tile (MI*32) x 128, BK=32, 8 warps (2 along M x 4 along N),
// warp tile (MI*16) x 32.  4-stage cp.async pipeline, 2 CTAs/SM.
// ---------------------------------------------------------------------------
#define BK 32
#define SA  40      // halves: 32 + 8 pad (A tile and mode0 B tile rows)
#define SB1 136     // halves: 128 + 8 pad (mode1 B tile rows)
#define NSTAGE 4

template<int MODEB, int MI>
__global__ __launch_bounds__(256, 2) void hgemm(
    const __half* __restrict__ A, const __half* __restrict__ B,
    float* __restrict__ C32, __half* __restrict__ C16,
    int M, int N, int K, int KB,
    int ldA, int ldB, int ldC32, int ldC16, float alpha)
{
    constexpr int BM = MI * 32;
    constexpr int A_BYT = BM * SA * 2;
    constexpr int B_BYT = MODEB ? (32 * SB1 * 2) : (128 * SA * 2);
    constexpr int STG = A_BYT + B_BYT;
    constexpr int ACH = BM * 4 / 256;     // A 16B-chunk iterations per thread

    extern __shared__ char smem[];
    const uint32_t sb = smem_to_u32(smem);

    const int tid = threadIdx.x;
    const int lane = tid & 31, w = tid >> 5;
    const int wm = w & 1, wn = w >> 1;                // 2 x 4 warp grid
    const int bm = blockIdx.y * BM, bn = blockIdx.x * 128;
    const int nIter = K / BK;

    float acc[MI][4][4];
#pragma unroll
    for (int i = 0; i < MI; i++)
#pragma unroll
        for (int j = 0; j < 4; j++)
#pragma unroll
            for (int t = 0; t < 4; t++) acc[i][j][t] = 0.f;

    auto load = [&](int s, int buf) {
        const int k0 = s * BK;
        const uint32_t aS = sb + (uint32_t)buf * STG;
        const uint32_t bS = aS + A_BYT;
#pragma unroll
        for (int i = 0; i < ACH; i++) {               // A: BM rows x 64B
            int ch = tid + 256 * i;
            int r = ch >> 2, cb = ch & 3;
            uint32_t sa = aS + (r * SA + cb * 8) * 2;
            int gr = bm + r;
            cp16(sa, A + (size_t)gr * ldA + k0 + cb * 8, gr < M);
        }
        if (MODEB) {
#pragma unroll
            for (int i = 0; i < 2; i++) {             // B: 32 k-rows x 256B
                int ch = tid + 256 * i;
                int r = ch >> 4, cb = ch & 15;
                uint32_t sa = bS + (r * SB1 + cb * 8) * 2;
                int gk = k0 + r;
                cp16(sa, B + (size_t)gk * ldB + bn + cb * 8, gk < KB);
            }
        } else {
#pragma unroll
            for (int i = 0; i < 2; i++) {             // B: 128 n-rows x 64B
                int ch = tid + 256 * i;
                int r = ch >> 2, cb = ch & 3;
                uint32_t sa = bS + (r * SA + cb * 8) * 2;
                int gn = bn + r;
                cp16(sa, B + (size_t)gn * ldB + k0 + cb * 8, gn < N);
            }
        }
        asm volatile("cp.async.commit_group;" ::: "memory");
    };

    load(0, 0);
    load(1, 1);
    load(2, 2);

    const int arow  = lane & 15;
    const int acol  = (lane >> 4) * 8;
    const int b0row = (lane & 7) + ((lane >> 4) & 1) * 8;   // mode0 (no trans)
    const int b0col = ((lane >> 3) & 1) * 8;
    const int b1row = (lane & 7) + ((lane >> 3) & 1) * 8;   // mode1 (.trans)
    const int b1col = ((lane >> 4) & 1) * 8;

    for (int it = 0; it < nIter; ++it) {
        asm volatile("cp.async.wait_group 2;" ::: "memory");
        __syncthreads();
        const uint32_t aS = sb + (uint32_t)(it & 3) * STG;
        const uint32_t bS = aS + A_BYT;

#pragma unroll
        for (int kk = 0; kk < 2; kk++) {
            uint32_t a[MI][4];
#pragma unroll
            for (int mi = 0; mi < MI; mi++) {
                uint32_t addr = aS + (uint32_t)((((wm * MI + mi) * 16 + arow) * SA) + kk * 16 + acol) * 2;
                ldsm4(a[mi][0], a[mi][1], a[mi][2], a[mi][3], addr);
            }
            uint32_t b[2][4];
#pragma unroll
            for (int nb = 0; nb < 2; nb++) {
                if (MODEB) {
                    uint32_t addr = bS + (uint32_t)(((kk * 16 + b1row) * SB1) + wn * 32 + nb * 16 + b1col) * 2;
                    ldsm4t(b[nb][0], b[nb][1], b[nb][2], b[nb][3], addr);
                } else {
                    uint32_t addr = bS + (uint32_t)(((wn * 32 + nb * 16 + b0row) * SA) + kk * 16 + b0col) * 2;
                    ldsm4(b[nb][0], b[nb][1], b[nb][2], b[nb][3], addr);
                }
            }
#pragma unroll
            for (int mi = 0; mi < MI; mi++)
#pragma unroll
                for (int nj = 0; nj < 4; nj++)
                    mma16816(acc[mi][nj], a[mi],
                             b[nj >> 1][2 * (nj & 1)], b[nj >> 1][2 * (nj & 1) + 1]);
        }
        if (it + 3 < nIter) load(it + 3, (it + 3) & 3);
        else asm volatile("cp.async.commit_group;" ::: "memory");
    }

    // ---- epilogue: direct register stores ------------------------------
#pragma unroll
    for (int mi = 0; mi < MI; mi++) {
        const int r0 = bm + (wm * MI + mi) * 16 + (lane >> 2);
#pragma unroll
        for (int nj = 0; nj < 4; nj++) {
            const int c0 = bn + wn * 32 + nj * 8 + 2 * (lane & 3);
            const float* ac = acc[mi][nj];
            if (C32) {
                if (r0 < M && c0 < N)
                    *(float2*)(C32 + (size_t)r0 * ldC32 + c0) =
                        make_float2(ac[0] * alpha, ac[1] * alpha);
                if (r0 + 8 < M && c0 < N)
                    *(float2*)(C32 + (size_t)(r0 + 8) * ldC32 + c0) =
                        make_float2(ac[2] * alpha, ac[3] * alpha);
            }
            if (C16) {
                if (r0 < M && c0 < N)
                    *(__half2*)(C16 + (size_t)r0 * ldC16 + c0) =
                        __floats2half2_rn(ac[0] * alpha, ac[1] * alpha);
                if (r0 + 8 < M && c0 < N)
                    *(__half2*)(C16 + (size_t)(r0 + 8) * ldC16 + c0) =
                        __floats2half2_rn(ac[2] * alpha, ac[3] * alpha);
            }
        }
    }
}

// ---------------------------------------------------------------------------
// fp32 -> fp16 conversion kernels
// ---------------------------------------------------------------------------
__global__ void cvt1(const float4* __restrict__ s, __half2* __restrict__ d, int n4) {
    int i = blockIdx.x * blockDim.x + threadIdx.x;
    if (i < n4) {
        float4 v = s[i];
        d[2 * i]     = __floats2half2_rn(v.x, v.y);
        d[2 * i + 1] = __floats2half2_rn(v.z, v.w);
    }
}
__global__ void cvt_fuse3(const float4* __restrict__ q, const float4* __restrict__ k,
                          const float4* __restrict__ v, __half* __restrict__ d) {
    int i = blockIdx.x * blockDim.x + threadIdx.x;     // over 2048*2048/4
    if (i < DM * DM / 4) {
        int p = i * 4;
        int row = p >> 11, col = p & 2047;
        float4 a;
        __half2* dq = (__half2*)(d + (size_t)row * NQKV + col);
        a = q[i]; dq[0] = __floats2half2_rn(a.x, a.y); dq[1] = __floats2half2_rn(a.z, a.w);
        __half2* dk = (__half2*)(d + (size_t)row * NQKV + 2048 + col);
        a = k[i]; dk[0] = __floats2half2_rn(a.x, a.y); dk[1] = __floats2half2_rn(a.z, a.w);
        __half2* dv = (__half2*)(d + (size_t)row * NQKV + 4096 + col);
        a = v[i]; dv[0] = __floats2half2_rn(a.x, a.y); dv[1] = __floats2half2_rn(a.z, a.w);
    }
}

// ---------------------------------------------------------------------------
// QR[i, r] = scale * (Q[i] . wk[r]).  wk cached in smem; Q fp16.
// ---------------------------------------------------------------------------
#define QR_BLOCKS 25
#define QR_ROWS   20
#define QR_THREADS (NREL * 32)  // 672
#define QR_SMEM ((NREL * DM + DM) * 4)

__global__ __launch_bounds__(QR_THREADS, 1) void qr_kernel(
    const __half* __restrict__ Q, int ldQ, const float* __restrict__ wk,
    float* __restrict__ QR, float scale)
{
    extern __shared__ float qsm[];
    float* wks = qsm;
    float* qv  = qsm + NREL * DM;
    const int tid = threadIdx.x, warp = tid / 32, lane = tid & 31;

    for (int t = tid; t < NREL * DM; t += QR_THREADS) wks[t] = wk[t];
    __syncthreads();

    for (int ii = 0; ii < QR_ROWS; ii++) {
        const int i = blockIdx.x * QR_ROWS + ii;
        for (int t = tid; t < DM; t += QR_THREADS)
            qv[t] = __half2float(Q[(size_t)i * ldQ + t]);
        __syncthreads();
        if (warp < NREL) {
            float s = 0.f;
            const float* wp = wks + warp * DM;
#pragma unroll 4
            for (int k = lane; k < DM; k += 32) s += qv[k] * wp[k];
#pragma unroll
            for (int o = 16; o > 0; o >>= 1) s += __shfl_xor_sync(0xffffffffu, s, o);
            if (lane == 0) QR[i * NREL + warp] = s * scale;
        }
        __syncthreads();
    }
}

// ---------------------------------------------------------------------------
// Fused bias + mask + softmax.  Reads fp32 S; writes fp32 Aout and fp16 A16.
// ---------------------------------------------------------------------------
__global__ __launch_bounds__(512) void softmax_kernel(
    float* __restrict__ S, const float* __restrict__ QR,
    const int* __restrict__ mask, float* __restrict__ Aout,
    __half* __restrict__ A16, int n)
{
    const int i = blockIdx.x;
    __shared__ float red[512];
    float* row = S + (size_t)i * n;
    const int* mrow = mask + (size_t)i * n;
    float* arow = Aout + (size_t)i * n;
    __half* hrow = A16 + (size_t)i * NTOKP;

    float m = -INFINITY;
    for (int j = threadIdx.x; j < n; j += blockDim.x) {
        int d = j - i;
        d = min(max(d, -KWIN), KWIN);
        float v = row[j] + QR[i * NREL + d + KWIN];
        if (mrow[j] == 0) v = -1e9f;
        row[j] = v;
        m = fmaxf(m, v);
    }
    red[threadIdx.x] = m;
    __syncthreads();
    for (int s = 256; s > 0; s >>= 1) {
        if (threadIdx.x < s) red[threadIdx.x] = fmaxf(red[threadIdx.x], red[threadIdx.x + s]);
        __syncthreads();
    }
    m = red[0];
    __syncthreads();

    float sum = 0.f;
    for (int j = threadIdx.x; j < n; j += blockDim.x) {
        float e = expf(row[j] - m);
        row[j] = e;
        sum += e;
    }
    red[threadIdx.x] = sum;
    __syncthreads();
    for (int s = 256; s > 0; s >>= 1) {
        if (threadIdx.x < s) red[threadIdx.x] += red[threadIdx.x + s];
        __syncthreads();
    }
    const float inv = 1.0f / red[0];
    __syncthreads();

    for (int j = threadIdx.x; j < n; j += blockDim.x) {
        float a = row[j] * inv;
        arow[j] = a;
        hrow[j] = __float2half_rn(a);
    }
    for (int j = n + threadIdx.x; j < NTOKP; j += blockDim.x) hrow[j] = __float2half_rn(0.f);
}

// ---------------------------------------------------------------------------
extern "C" void kernel_launch(void* const* d_in, const int* in_sizes, int n_in,
                              void* d_out, int out_size)
{
    const float* X    = (const float*)d_in[0];
    const int*   mask = (const int*)  d_in[1];
    const float* Wq   = (const float*)d_in[2];
    const float* Wk   = (const float*)d_in[3];
    const float* Wv   = (const float*)d_in[4];
    const float* Wo   = (const float*)d_in[5];
    const float* wk   = (const float*)d_in[6];

    float* Y    = (float*)d_out;                 // [500, 2048]
    float* Aout = Y + (size_t)NTOK * DM;         // [500, 500]

    __half *X16, *W16, *Wo16, *QKV16, *A16, *T16;
    float *S, *QR;
    cudaGetSymbolAddress((void**)&X16,   g_X16);
    cudaGetSymbolAddress((void**)&W16,   g_W16);
    cudaGetSymbolAddress((void**)&Wo16,  g_Wo16);
    cudaGetSymbolAddress((void**)&QKV16, g_QKV16);
    cudaGetSymbolAddress((void**)&A16,   g_A16);
    cudaGetSymbolAddress((void**)&T16,   g_T16);
    cudaGetSymbolAddress((void**)&S,     g_S);
    cudaGetSymbolAddress((void**)&QR,    g_QR);

    // smem sizes: stage = A + B
    const int SM_1_4 = NSTAGE * (128 * SA * 2 + 32 * SB1 * 2);   // 75776
    const int SM_0_2 = NSTAGE * (64 * SA * 2 + 128 * SA * 2);    // 61440
    const int SM_1_2 = NSTAGE * (64 * SA * 2 + 32 * SB1 * 2);    // 55296
    cudaFuncSetAttribute((const void*)hgemm<1,4>, cudaFuncAttributeMaxDynamicSharedMemorySize, SM_1_4);
    cudaFuncSetAttribute((const void*)hgemm<0,2>, cudaFuncAttributeMaxDynamicSharedMemorySize, SM_0_2);
    cudaFuncSetAttribute((const void*)hgemm<1,2>, cudaFuncAttributeMaxDynamicSharedMemorySize, SM_1_2);
    cudaFuncSetAttribute((const void*)qr_kernel,  cudaFuncAttributeMaxDynamicSharedMemorySize, QR_SMEM);

    const float scale = 1.0f / sqrtf((float)DM);

    // 0) fp32 -> fp16 conversions
    cvt1<<<(NTOK * DM / 4 + 255) / 256, 256>>>((const float4*)X, (__half2*)X16, NTOK * DM / 4);
    cvt_fuse3<<<(DM * DM / 4 + 255) / 256, 256>>>(
        (const float4*)Wq, (const float4*)Wk, (const float4*)Wv, W16);
    cvt1<<<(DM * DM / 4 + 255) / 256, 256>>>((const float4*)Wo, (__half2*)Wo16, DM * DM / 4);

    // 1) QKV = X @ [Wq|Wk|Wv]   (fp16 out)  grid 48x4 = 192 CTAs
    hgemm<1,4><<<dim3(NQKV / 128, 4), 256, SM_1_4>>>(
        X16, W16, nullptr, QKV16, NTOK, NQKV, DM, DM, DM, NQKV, 0, NQKV, 1.0f);

    // 2) QR = scale * Q @ wk^T
    qr_kernel<<<QR_BLOCKS, QR_THREADS, QR_SMEM>>>(QKV16, NQKV, wk, QR, scale);

    // 3) S = scale * Q @ K^T    (fp32 out)  grid 4x8 = 32 CTAs
    hgemm<0,2><<<dim3(4, 8), 256, SM_0_2>>>(
        QKV16, QKV16 + DM, S, nullptr, NTOK, NTOK, DM, DM, NQKV, NQKV, NTOK, 0, scale);

    // 4) bias + mask + softmax  (fp32 Aout + fp16 A16)
    softmax_kernel<<<NTOK, 512>>>(S, QR, mask, Aout, A16, NTOK);

    // 5) T = A @ V   (K padded to 512; V rows >=500 zero-filled)  grid 16x8 = 128 CTAs
    hgemm<1,2><<<dim3(DM / 128, 8), 256, SM_1_2>>>(
        A16, QKV16 + 2 * DM, nullptr, T16, NTOK, DM, NTOKP, NTOK, NTOKP, NQKV, 0, DM, 1.0f);

    // 6) Y = T @ Wo             (fp32 out)  grid 16x8 = 128 CTAs
    hgemm<1,2><<<dim3(DM / 128, 8), 256, SM_1_2>>>(
        T16, Wo16, Y, nullptr, NTOK, DM, DM, DM, DM, DM, DM, 0, 1.0f);
}

// round 6
// speedup vs baseline: 9.9250x; 1.0473x over previous
#include <cuda_runtime.h>
#include <cuda_fp16.h>
#include <cstdint>
#include <math.h>

#define NTOK  500
#define NTOKP 512
#define DM    2048
#define KWIN  10
#define NREL  21
#define NQKV  6144

// ---------------- scratch (device globals; no allocation allowed) ----------
__device__ __align__(16) __half g_X16 [NTOK * DM];
__device__ __align__(16) __half g_W16 [DM * NQKV];     // [k][Wq|Wk|Wv]
__device__ __align__(16) __half g_Wo16[DM * DM];
__device__ __align__(16) __half g_QKV16[NTOK * NQKV];  // [tok][Q|K|V]
__device__ __align__(16) __half g_A16 [NTOK * NTOKP];  // attention, zero-padded cols
__device__ __align__(16) __half g_T16 [NTOK * DM];
__device__ float g_S [NTOK * NTOK];
__device__ float g_QR[NTOK * NREL];

// ---------------- PTX helpers ----------------------------------------------
__device__ __forceinline__ uint32_t smem_to_u32(const void* p) {
    uint32_t a;
    asm("{ .reg .u64 t; cvta.to.shared.u64 t, %1; cvt.u32.u64 %0, t; }" : "=r"(a) : "l"(p));
    return a;
}
__device__ __forceinline__ void cp16(uint32_t sa, const void* g, bool v) {
    asm volatile("cp.async.ca.shared.global [%0], [%1], 16, %2;"
                 :: "r"(sa), "l"(g), "r"(v ? 16u : 0u) : "memory");
}
__device__ __forceinline__ void ldsm4(uint32_t& r0, uint32_t& r1, uint32_t& r2, uint32_t& r3,
                                      uint32_t addr) {
    asm volatile("ldmatrix.sync.aligned.m8n8.x4.shared.b16 {%0,%1,%2,%3}, [%4];"
                 : "=r"(r0), "=r"(r1), "=r"(r2), "=r"(r3) : "r"(addr));
}
__device__ __forceinline__ void ldsm4t(uint32_t& r0, uint32_t& r1, uint32_t& r2, uint32_t& r3,
                                       uint32_t addr) {
    asm volatile("ldmatrix.sync.aligned.m8n8.x4.trans.shared.b16 {%0,%1,%2,%3}, [%4];"
                 : "=r"(r0), "=r"(r1), "=r"(r2), "=r"(r3) : "r"(addr));
}
__device__ __forceinline__ void mma16816(float* c, const uint32_t* a, uint32_t b0, uint32_t b1) {
    asm volatile("mma.sync.aligned.m16n8k16.row.col.f32.f16.f16.f32 "
                 "{%0,%1,%2,%3}, {%4,%5,%6,%7}, {%8,%9}, {%0,%1,%2,%3};"
                 : "+f"(c[0]), "+f"(c[1]), "+f"(c[2]), "+f"(c[3])
                 : "r"(a[0]), "r"(a[1]), "r"(a[2]), "r"(a[3]), "r"(b0), "r"(b1));
}

// ---------------------------------------------------------------------------
// fp16 GEMM, fp32 accumulate.  C = alpha * A[M,K] @ op(B)
//   MODEB=0: B [N][K] row-major => C = A @ B^T   (S = Q K^T)
//   MODEB=1: B [K][N] row-major => C = A @ B     (weights / V)
// CTA tile (MI*32) x 128, BK=64, 8 warps (2 along M x 4 along N),
// warp tile (MI*16) x 32.  3-stage cp.async pipeline, 2 CTAs/SM.
// ---------------------------------------------------------------------------
#define BK 64
#define SA  72      // halves per row: 64 + 8 pad (A and mode0 B tiles)
#define SB1 136     // halves per row: 128 + 8 pad (mode1 B tile)
#define NSTAGE 3

template<int MODEB, int MI>
__global__ __launch_bounds__(256, 2) void hgemm(
    const __half* __restrict__ A, const __half* __restrict__ B,
    float* __restrict__ C32, __half* __restrict__ C16,
    int M, int N, int K, int KB,
    int ldA, int ldB, int ldC32, int ldC16, float alpha)
{
    constexpr int BM = MI * 32;
    constexpr int A_BYT = BM * SA * 2;
    constexpr int B_BYT = MODEB ? (64 * SB1 * 2) : (128 * SA * 2);
    constexpr int STG = A_BYT + B_BYT;
    constexpr int ACH = BM * 8 / 256;     // A 16B-chunk iterations per thread

    extern __shared__ char smem[];
    const uint32_t sb = smem_to_u32(smem);

    const int tid = threadIdx.x;
    const int lane = tid & 31, w = tid >> 5;
    const int wm = w & 1, wn = w >> 1;                // 2 x 4 warp grid
    const int bm = blockIdx.y * BM, bn = blockIdx.x * 128;
    const int nIter = K / BK;

    float acc[MI][4][4];
#pragma unroll
    for (int i = 0; i < MI; i++)
#pragma unroll
        for (int j = 0; j < 4; j++)
#pragma unroll
            for (int t = 0; t < 4; t++) acc[i][j][t] = 0.f;

    auto load = [&](int s, int buf) {
        const int k0 = s * BK;
        const uint32_t aS = sb + (uint32_t)buf * STG;
        const uint32_t bS = aS + A_BYT;
#pragma unroll
        for (int i = 0; i < ACH; i++) {               // A: BM rows x 128B
            int ch = tid + 256 * i;
            int r = ch >> 3, cb = ch & 7;
            uint32_t sa = aS + (r * SA + cb * 8) * 2;
            int gr = bm + r;
            cp16(sa, A + (size_t)gr * ldA + k0 + cb * 8, gr < M);
        }
        if (MODEB) {
#pragma unroll
            for (int i = 0; i < 4; i++) {             // B: 64 k-rows x 256B
                int ch = tid + 256 * i;
                int r = ch >> 4, cb = ch & 15;
                uint32_t sa = bS + (r * SB1 + cb * 8) * 2;
                int gk = k0 + r;
                cp16(sa, B + (size_t)gk * ldB + bn + cb * 8, gk < KB);
            }
        } else {
#pragma unroll
            for (int i = 0; i < 4; i++) {             // B: 128 n-rows x 128B
                int ch = tid + 256 * i;
                int r = ch >> 3, cb = ch & 7;
                uint32_t sa = bS + (r * SA + cb * 8) * 2;
                int gn = bn + r;
                cp16(sa, B + (size_t)gn * ldB + k0 + cb * 8, gn < N);
            }
        }
        asm volatile("cp.async.commit_group;" ::: "memory");
    };

    load(0, 0);
    load(1, 1);

    const int arow  = lane & 15;
    const int acol  = (lane >> 4) * 8;
    const int b0row = (lane & 7) + ((lane >> 4) & 1) * 8;   // mode0 (no trans)
    const int b0col = ((lane >> 3) & 1) * 8;
    const int b1row = (lane & 7) + ((lane >> 3) & 1) * 8;   // mode1 (.trans)
    const int b1col = ((lane >> 4) & 1) * 8;

    for (int it = 0; it < nIter; ++it) {
        asm volatile("cp.async.wait_group 1;" ::: "memory");
        __syncthreads();
        const uint32_t aS = sb + (uint32_t)(it % NSTAGE) * STG;
        const uint32_t bS = aS + A_BYT;

#pragma unroll
        for (int kk = 0; kk < 4; kk++) {
            uint32_t a[MI][4];
#pragma unroll
            for (int mi = 0; mi < MI; mi++) {
                uint32_t addr = aS + (uint32_t)((((wm * MI + mi) * 16 + arow) * SA) + kk * 16 + acol) * 2;
                ldsm4(a[mi][0], a[mi][1], a[mi][2], a[mi][3], addr);
            }
            uint32_t b[2][4];
#pragma unroll
            for (int nb = 0; nb < 2; nb++) {
                if (MODEB) {
                    uint32_t addr = bS + (uint32_t)(((kk * 16 + b1row) * SB1) + wn * 32 + nb * 16 + b1col) * 2;
                    ldsm4t(b[nb][0], b[nb][1], b[nb][2], b[nb][3], addr);
                } else {
                    uint32_t addr = bS + (uint32_t)(((wn * 32 + nb * 16 + b0row) * SA) + kk * 16 + b0col) * 2;
                    ldsm4(b[nb][0], b[nb][1], b[nb][2], b[nb][3], addr);
                }
            }
#pragma unroll
            for (int mi = 0; mi < MI; mi++)
#pragma unroll
                for (int nj = 0; nj < 4; nj++)
                    mma16816(acc[mi][nj], a[mi],
                             b[nj >> 1][2 * (nj & 1)], b[nj >> 1][2 * (nj & 1) + 1]);
        }
        __syncthreads();
        if (it + 2 < nIter) load(it + 2, (it + 2) % NSTAGE);
        else asm volatile("cp.async.commit_group;" ::: "memory");
    }

    // ---- epilogue: direct register stores ------------------------------
#pragma unroll
    for (int mi = 0; mi < MI; mi++) {
        const int r0 = bm + (wm * MI + mi) * 16 + (lane >> 2);
#pragma unroll
        for (int nj = 0; nj < 4; nj++) {
            const int c0 = bn + wn * 32 + nj * 8 + 2 * (lane & 3);
            const float* ac = acc[mi][nj];
            if (C32) {
                if (r0 < M && c0 < N)
                    *(float2*)(C32 + (size_t)r0 * ldC32 + c0) =
                        make_float2(ac[0] * alpha, ac[1] * alpha);
                if (r0 + 8 < M && c0 < N)
                    *(float2*)(C32 + (size_t)(r0 + 8) * ldC32 + c0) =
                        make_float2(ac[2] * alpha, ac[3] * alpha);
            }
            if (C16) {
                if (r0 < M && c0 < N)
                    *(__half2*)(C16 + (size_t)r0 * ldC16 + c0) =
                        __floats2half2_rn(ac[0] * alpha, ac[1] * alpha);
                if (r0 + 8 < M && c0 < N)
                    *(__half2*)(C16 + (size_t)(r0 + 8) * ldC16 + c0) =
                        __floats2half2_rn(ac[2] * alpha, ac[3] * alpha);
            }
        }
    }
}

// ---------------------------------------------------------------------------
// fp32 -> fp16 conversion kernels
// ---------------------------------------------------------------------------
__global__ void cvt1(const float4* __restrict__ s, __half2* __restrict__ d, int n4) {
    int i = blockIdx.x * blockDim.x + threadIdx.x;
    if (i < n4) {
        float4 v = s[i];
        d[2 * i]     = __floats2half2_rn(v.x, v.y);
        d[2 * i + 1] = __floats2half2_rn(v.z, v.w);
    }
}
__global__ void cvt_fuse3(const float4* __restrict__ q, const float4* __restrict__ k,
                          const float4* __restrict__ v, __half* __restrict__ d) {
    int i = blockIdx.x * blockDim.x + threadIdx.x;     // over 2048*2048/4
    if (i < DM * DM / 4) {
        int p = i * 4;
        int row = p >> 11, col = p & 2047;
        float4 a;
        __half2* dq = (__half2*)(d + (size_t)row * NQKV + col);
        a = q[i]; dq[0] = __floats2half2_rn(a.x, a.y); dq[1] = __floats2half2_rn(a.z, a.w);
        __half2* dk = (__half2*)(d + (size_t)row * NQKV + 2048 + col);
        a = k[i]; dk[0] = __floats2half2_rn(a.x, a.y); dk[1] = __floats2half2_rn(a.z, a.w);
        __half2* dv = (__half2*)(d + (size_t)row * NQKV + 4096 + col);
        a = v[i]; dv[0] = __floats2half2_rn(a.x, a.y); dv[1] = __floats2half2_rn(a.z, a.w);
    }
}

// ---------------------------------------------------------------------------
// QR[i, r] = scale * (Q[i] . wk[r]).  wk cached in smem; Q fp16.
// ---------------------------------------------------------------------------
#define QR_BLOCKS 25
#define QR_ROWS   20
#define QR_THREADS (NREL * 32)  // 672
#define QR_SMEM ((NREL * DM + DM) * 4)

__global__ __launch_bounds__(QR_THREADS, 1) void qr_kernel(
    const __half* __restrict__ Q, int ldQ, const float* __restrict__ wk,
    float* __restrict__ QR, float scale)
{
    extern __shared__ float qsm[];
    float* wks = qsm;
    float* qv  = qsm + NREL * DM;
    const int tid = threadIdx.x, warp = tid / 32, lane = tid & 31;

    for (int t = tid; t < NREL * DM; t += QR_THREADS) wks[t] = wk[t];
    __syncthreads();

    for (int ii = 0; ii < QR_ROWS; ii++) {
        const int i = blockIdx.x * QR_ROWS + ii;
        for (int t = tid; t < DM; t += QR_THREADS)
            qv[t] = __half2float(Q[(size_t)i * ldQ + t]);
        __syncthreads();
        if (warp < NREL) {
            float s = 0.f;
            const float* wp = wks + warp * DM;
#pragma unroll 4
            for (int k = lane; k < DM; k += 32) s += qv[k] * wp[k];
#pragma unroll
            for (int o = 16; o > 0; o >>= 1) s += __shfl_xor_sync(0xffffffffu, s, o);
            if (lane == 0) QR[i * NREL + warp] = s * scale;
        }
        __syncthreads();
    }
}

// ---------------------------------------------------------------------------
// Fused bias + mask + softmax.  Reads fp32 S; writes fp32 Aout and fp16 A16.
// ---------------------------------------------------------------------------
__global__ __launch_bounds__(512) void softmax_kernel(
    float* __restrict__ S, const float* __restrict__ QR,
    const int* __restrict__ mask, float* __restrict__ Aout,
    __half* __restrict__ A16, int n)
{
    const int i = blockIdx.x;
    __shared__ float red[512];
    float* row = S + (size_t)i * n;
    const int* mrow = mask + (size_t)i * n;
    float* arow = Aout + (size_t)i * n;
    __half* hrow = A16 + (size_t)i * NTOKP;

    float m = -INFINITY;
    for (int j = threadIdx.x; j < n; j += blockDim.x) {
        int d = j - i;
        d = min(max(d, -KWIN), KWIN);
        float v = row[j] + QR[i * NREL + d + KWIN];
        if (mrow[j] == 0) v = -1e9f;
        row[j] = v;
        m = fmaxf(m, v);
    }
    red[threadIdx.x] = m;
    __syncthreads();
    for (int s = 256; s > 0; s >>= 1) {
        if (threadIdx.x < s) red[threadIdx.x] = fmaxf(red[threadIdx.x], red[threadIdx.x + s]);
        __syncthreads();
    }
    m = red[0];
    __syncthreads();

    float sum = 0.f;
    for (int j = threadIdx.x; j < n; j += blockDim.x) {
        float e = expf(row[j] - m);
        row[j] = e;
        sum += e;
    }
    red[threadIdx.x] = sum;
    __syncthreads();
    for (int s = 256; s > 0; s >>= 1) {
        if (threadIdx.x < s) red[threadIdx.x] += red[threadIdx.x + s];
        __syncthreads();
    }
    const float inv = 1.0f / red[0];
    __syncthreads();

    for (int j = threadIdx.x; j < n; j += blockDim.x) {
        float a = row[j] * inv;
        arow[j] = a;
        hrow[j] = __float2half_rn(a);
    }
    for (int j = n + threadIdx.x; j < NTOKP; j += blockDim.x) hrow[j] = __float2half_rn(0.f);
}

// ---------------------------------------------------------------------------
extern "C" void kernel_launch(void* const* d_in, const int* in_sizes, int n_in,
                              void* d_out, int out_size)
{
    const float* X    = (const float*)d_in[0];
    const int*   mask = (const int*)  d_in[1];
    const float* Wq   = (const float*)d_in[2];
    const float* Wk   = (const float*)d_in[3];
    const float* Wv   = (const float*)d_in[4];
    const float* Wo   = (const float*)d_in[5];
    const float* wk   = (const float*)d_in[6];

    float* Y    = (float*)d_out;                 // [500, 2048]
    float* Aout = Y + (size_t)NTOK * DM;         // [500, 500]

    __half *X16, *W16, *Wo16, *QKV16, *A16, *T16;
    float *S, *QR;
    cudaGetSymbolAddress((void**)&X16,   g_X16);
    cudaGetSymbolAddress((void**)&W16,   g_W16);
    cudaGetSymbolAddress((void**)&Wo16,  g_Wo16);
    cudaGetSymbolAddress((void**)&QKV16, g_QKV16);
    cudaGetSymbolAddress((void**)&A16,   g_A16);
    cudaGetSymbolAddress((void**)&T16,   g_T16);
    cudaGetSymbolAddress((void**)&S,     g_S);
    cudaGetSymbolAddress((void**)&QR,    g_QR);

    // smem sizes: NSTAGE * (A + B) bytes
    const int SM_1_4 = NSTAGE * (128 * SA * 2 + 64 * SB1 * 2);   // 107520
    const int SM_0_2 = NSTAGE * (64 * SA * 2 + 128 * SA * 2);    // 82944
    const int SM_1_2 = NSTAGE * (64 * SA * 2 + 64 * SB1 * 2);    // 79872
    cudaFuncSetAttribute((const void*)hgemm<1,4>, cudaFuncAttributeMaxDynamicSharedMemorySize, SM_1_4);
    cudaFuncSetAttribute((const void*)hgemm<0,2>, cudaFuncAttributeMaxDynamicSharedMemorySize, SM_0_2);
    cudaFuncSetAttribute((const void*)hgemm<1,2>, cudaFuncAttributeMaxDynamicSharedMemorySize, SM_1_2);
    cudaFuncSetAttribute((const void*)qr_kernel,  cudaFuncAttributeMaxDynamicSharedMemorySize, QR_SMEM);

    const float scale = 1.0f / sqrtf((float)DM);

    // 0) fp32 -> fp16 conversions
    cvt1<<<(NTOK * DM / 4 + 255) / 256, 256>>>((const float4*)X, (__half2*)X16, NTOK * DM / 4);
    cvt_fuse3<<<(DM * DM / 4 + 255) / 256, 256>>>(
        (const float4*)Wq, (const float4*)Wk, (const float4*)Wv, W16);
    cvt1<<<(DM * DM / 4 + 255) / 256, 256>>>((const float4*)Wo, (__half2*)Wo16, DM * DM / 4);

    // 1) QKV = X @ [Wq|Wk|Wv]   (fp16 out)  grid 48x4 = 192 CTAs
    hgemm<1,4><<<dim3(NQKV / 128, 4), 256, SM_1_4>>>(
        X16, W16, nullptr, QKV16, NTOK, NQKV, DM, DM, DM, NQKV, 0, NQKV, 1.0f);

    // 2) QR = scale * Q @ wk^T
    qr_kernel<<<QR_BLOCKS, QR_THREADS, QR_SMEM>>>(QKV16, NQKV, wk, QR, scale);

    // 3) S = scale * Q @ K^T    (fp32 out)  grid 4x8 = 32 CTAs
    hgemm<0,2><<<dim3(4, 8), 256, SM_0_2>>>(
        QKV16, QKV16 + DM, S, nullptr, NTOK, NTOK, DM, DM, NQKV, NQKV, NTOK, 0, scale);

    // 4) bias + mask + softmax  (fp32 Aout + fp16 A16)
    softmax_kernel<<<NTOK, 512>>>(S, QR, mask, Aout, A16, NTOK);

    // 5) T = A @ V   (K padded to 512; V rows >=500 zero-filled)  grid 16x8 = 128 CTAs
    hgemm<1,2><<<dim3(DM / 128, 8), 256, SM_1_2>>>(
        A16, QKV16 + 2 * DM, nullptr, T16, NTOK, DM, NTOKP, NTOK, NTOKP, NQKV, 0, DM, 1.0f);

    // 6) Y = T @ Wo             (fp32 out)  grid 16x8 = 128 CTAs
    hgemm<1,2><<<dim3(DM / 128, 8), 256, SM_1_2>>>(
        T16, Wo16, Y, nullptr, NTOK, DM, DM, DM, DM, DM, DM, 0, 1.0f);
}

// round 7
// speedup vs baseline: 10.7832x; 1.0865x over previous
#include <cuda_runtime.h>
#include <cuda_fp16.h>
#include <cstdint>
#include <math.h>

#define NTOK  500
#define NTOKP 512
#define DM    2048
#define KWIN  10
#define NREL  21
#define NQKV  6144
#define SPL_S 8

// ---------------- scratch (device globals; no allocation allowed) ----------
__device__ __align__(16) __half g_X16 [NTOK * DM];
__device__ __align__(16) __half g_W16 [DM * NQKV];     // [k][Wq|Wk|Wv]
__device__ __align__(16) __half g_Wo16[DM * DM];
__device__ __align__(16) __half g_QKV16[NTOK * NQKV];  // [tok][Q|K|V]
__device__ __align__(16) __half g_A16 [NTOK * NTOKP];  // attention, zero-padded cols
__device__ __align__(16) __half g_T16 [NTOK * DM];
__device__ __align__(16) float g_P [2 * NTOK * NQKV];  // split-K partials (max 24.6MB)
__device__ float g_S [NTOK * NTOK];
__device__ float g_QR[NTOK * NREL];

// ---------------- PTX helpers ----------------------------------------------
__device__ __forceinline__ uint32_t smem_to_u32(const void* p) {
    uint32_t a;
    asm("{ .reg .u64 t; cvta.to.shared.u64 t, %1; cvt.u32.u64 %0, t; }" : "=r"(a) : "l"(p));
    return a;
}
__device__ __forceinline__ void cp16(uint32_t sa, const void* g, bool v) {
    asm volatile("cp.async.ca.shared.global [%0], [%1], 16, %2;"
                 :: "r"(sa), "l"(g), "r"(v ? 16u : 0u) : "memory");
}
__device__ __forceinline__ void ldsm4(uint32_t& r0, uint32_t& r1, uint32_t& r2, uint32_t& r3,
                                      uint32_t addr) {
    asm volatile("ldmatrix.sync.aligned.m8n8.x4.shared.b16 {%0,%1,%2,%3}, [%4];"
                 : "=r"(r0), "=r"(r1), "=r"(r2), "=r"(r3) : "r"(addr));
}
__device__ __forceinline__ void ldsm4t(uint32_t& r0, uint32_t& r1, uint32_t& r2, uint32_t& r3,
                                       uint32_t addr) {
    asm volatile("ldmatrix.sync.aligned.m8n8.x4.trans.shared.b16 {%0,%1,%2,%3}, [%4];"
                 : "=r"(r0), "=r"(r1), "=r"(r2), "=r"(r3) : "r"(addr));
}
__device__ __forceinline__ void mma16816(float* c, const uint32_t* a, uint32_t b0, uint32_t b1) {
    asm volatile("mma.sync.aligned.m16n8k16.row.col.f32.f16.f16.f32 "
                 "{%0,%1,%2,%3}, {%4,%5,%6,%7}, {%8,%9}, {%0,%1,%2,%3};"
                 : "+f"(c[0]), "+f"(c[1]), "+f"(c[2]), "+f"(c[3])
                 : "r"(a[0]), "r"(a[1]), "r"(a[2]), "r"(a[3]), "r"(b0), "r"(b1));
}

// ---------------------------------------------------------------------------
// Split-K fp16 GEMM, fp32 accumulate, fp32 partial output.
//   P[z] = alpha * A[M, kOff:kOff+kLen] @ op(B)[same k range]
//   MODEB=0: B [N][K] row-major => A @ B^T     MODEB=1: B [K][N] row-major => A @ B
// CTA tile (MI*32) x 128, BK=64, 8 warps, 3-stage cp.async, 1 barrier/iter.
// ---------------------------------------------------------------------------
#define BK 64
#define SA  72      // halves per row: 64 + 8 pad
#define SB1 136     // halves per row: 128 + 8 pad
#define NSTAGE 3

template<int MODEB, int MI>
__global__ __launch_bounds__(256, 2) void hgemm(
    const __half* __restrict__ A, const __half* __restrict__ B,
    float* __restrict__ P,
    int M, int N, int kLen, int KB,
    int ldA, int ldB, int ldC, size_t chunkStride, float alpha)
{
    constexpr int BM = MI * 32;
    constexpr int A_BYT = BM * SA * 2;
    constexpr int B_BYT = MODEB ? (64 * SB1 * 2) : (128 * SA * 2);
    constexpr int STG = A_BYT + B_BYT;
    constexpr int ACH = BM * 8 / 256;

    extern __shared__ char smem[];
    const uint32_t sb = smem_to_u32(smem);

    const int tid = threadIdx.x;
    const int lane = tid & 31, w = tid >> 5;
    const int wm = w & 1, wn = w >> 1;
    const int bm = blockIdx.y * BM, bn = blockIdx.x * 128;
    const int kOff = blockIdx.z * kLen;
    const int nIter = kLen / BK;
    float* Cp = P + (size_t)blockIdx.z * chunkStride;

    float acc[MI][4][4];
#pragma unroll
    for (int i = 0; i < MI; i++)
#pragma unroll
        for (int j = 0; j < 4; j++)
#pragma unroll
            for (int t = 0; t < 4; t++) acc[i][j][t] = 0.f;

    auto load = [&](int s, int buf) {
        const int k0 = kOff + s * BK;
        const uint32_t aS = sb + (uint32_t)buf * STG;
        const uint32_t bS = aS + A_BYT;
#pragma unroll
        for (int i = 0; i < ACH; i++) {               // A: BM rows x 128B
            int ch = tid + 256 * i;
            int r = ch >> 3, cb = ch & 7;
            uint32_t sa = aS + (r * SA + cb * 8) * 2;
            int gr = bm + r;
            cp16(sa, A + (size_t)gr * ldA + k0 + cb * 8, gr < M);
        }
        if (MODEB) {
#pragma unroll
            for (int i = 0; i < 4; i++) {             // B: 64 k-rows x 256B
                int ch = tid + 256 * i;
                int r = ch >> 4, cb = ch & 15;
                uint32_t sa = bS + (r * SB1 + cb * 8) * 2;
                int gk = k0 + r;
                cp16(sa, B + (size_t)gk * ldB + bn + cb * 8, gk < KB);
            }
        } else {
#pragma unroll
            for (int i = 0; i < 4; i++) {             // B: 128 n-rows x 128B
                int ch = tid + 256 * i;
                int r = ch >> 3, cb = ch & 7;
                uint32_t sa = bS + (r * SA + cb * 8) * 2;
                int gn = bn + r;
                cp16(sa, B + (size_t)gn * ldB + k0 + cb * 8, gn < N);
            }
        }
        asm volatile("cp.async.commit_group;" ::: "memory");
    };

    load(0, 0);
    load(1, 1);

    const int arow  = lane & 15;
    const int acol  = (lane >> 4) * 8;
    const int b0row = (lane & 7) + ((lane >> 4) & 1) * 8;
    const int b0col = ((lane >> 3) & 1) * 8;
    const int b1row = (lane & 7) + ((lane >> 3) & 1) * 8;
    const int b1col = ((lane >> 4) & 1) * 8;

    for (int it = 0; it < nIter; ++it) {
        asm volatile("cp.async.wait_group 1;" ::: "memory");
        __syncthreads();
        // issue next stage load immediately (its buffer was consumed at it-1)
        if (it + 2 < nIter) load(it + 2, (it + 2) % NSTAGE);
        else asm volatile("cp.async.commit_group;" ::: "memory");

        const uint32_t aS = sb + (uint32_t)(it % NSTAGE) * STG;
        const uint32_t bS = aS + A_BYT;

#pragma unroll
        for (int kk = 0; kk < 4; kk++) {
            uint32_t a[MI][4];
#pragma unroll
            for (int mi = 0; mi < MI; mi++) {
                uint32_t addr = aS + (uint32_t)((((wm * MI + mi) * 16 + arow) * SA) + kk * 16 + acol) * 2;
                ldsm4(a[mi][0], a[mi][1], a[mi][2], a[mi][3], addr);
            }
            uint32_t b[2][4];
#pragma unroll
            for (int nb = 0; nb < 2; nb++) {
                if (MODEB) {
                    uint32_t addr = bS + (uint32_t)(((kk * 16 + b1row) * SB1) + wn * 32 + nb * 16 + b1col) * 2;
                    ldsm4t(b[nb][0], b[nb][1], b[nb][2], b[nb][3], addr);
                } else {
                    uint32_t addr = bS + (uint32_t)(((wn * 32 + nb * 16 + b0row) * SA) + kk * 16 + b0col) * 2;
                    ldsm4(b[nb][0], b[nb][1], b[nb][2], b[nb][3], addr);
                }
            }
#pragma unroll
            for (int mi = 0; mi < MI; mi++)
#pragma unroll
                for (int nj = 0; nj < 4; nj++)
                    mma16816(acc[mi][nj], a[mi],
                             b[nj >> 1][2 * (nj & 1)], b[nj >> 1][2 * (nj & 1) + 1]);
        }
        __syncthreads();   // all warps done with stage it%3 before it is reloaded
    }

    // ---- epilogue: fp32 partials -----------------------------------------
#pragma unroll
    for (int mi = 0; mi < MI; mi++) {
        const int r0 = bm + (wm * MI + mi) * 16 + (lane >> 2);
#pragma unroll
        for (int nj = 0; nj < 4; nj++) {
            const int c0 = bn + wn * 32 + nj * 8 + 2 * (lane & 3);
            const float* ac = acc[mi][nj];
            if (r0 < M && c0 < N)
                *(float2*)(Cp + (size_t)r0 * ldC + c0) =
                    make_float2(ac[0] * alpha, ac[1] * alpha);
            if (r0 + 8 < M && c0 < N)
                *(float2*)(Cp + (size_t)(r0 + 8) * ldC + c0) =
                    make_float2(ac[2] * alpha, ac[3] * alpha);
        }
    }
}

// ---------------------------------------------------------------------------
// Reductions of 2-way split-K partials (deterministic, no atomics)
// ---------------------------------------------------------------------------
__global__ void reduce2h(const float* __restrict__ P, size_t CH,
                         __half* __restrict__ out, int n4) {
    int i = blockIdx.x * blockDim.x + threadIdx.x;
    if (i < n4) {
        float4 a = *(const float4*)(P + 4 * (size_t)i);
        float4 b = *(const float4*)(P + CH + 4 * (size_t)i);
        __half2* o = (__half2*)(out + 4 * (size_t)i);
        o[0] = __floats2half2_rn(a.x + b.x, a.y + b.y);
        o[1] = __floats2half2_rn(a.z + b.z, a.w + b.w);
    }
}
__global__ void reduce2f(const float* __restrict__ P, size_t CH,
                         float* __restrict__ out, int n4) {
    int i = blockIdx.x * blockDim.x + threadIdx.x;
    if (i < n4) {
        float4 a = *(const float4*)(P + 4 * (size_t)i);
        float4 b = *(const float4*)(P + CH + 4 * (size_t)i);
        *(float4*)(out + 4 * (size_t)i) =
            make_float4(a.x + b.x, a.y + b.y, a.z + b.z, a.w + b.w);
    }
}

// ---------------------------------------------------------------------------
// fp32 -> fp16 conversion kernels
// ---------------------------------------------------------------------------
__global__ void cvt1(const float4* __restrict__ s, __half2* __restrict__ d, int n4) {
    int i = blockIdx.x * blockDim.x + threadIdx.x;
    if (i < n4) {
        float4 v = s[i];
        d[2 * i]     = __floats2half2_rn(v.x, v.y);
        d[2 * i + 1] = __floats2half2_rn(v.z, v.w);
    }
}
__global__ void cvt_fuse3(const float4* __restrict__ q, const float4* __restrict__ k,
                          const float4* __restrict__ v, __half* __restrict__ d) {
    int i = blockIdx.x * blockDim.x + threadIdx.x;
    if (i < DM * DM / 4) {
        int p = i * 4;
        int row = p >> 11, col = p & 2047;
        float4 a;
        __half2* dq = (__half2*)(d + (size_t)row * NQKV + col);
        a = q[i]; dq[0] = __floats2half2_rn(a.x, a.y); dq[1] = __floats2half2_rn(a.z, a.w);
        __half2* dk = (__half2*)(d + (size_t)row * NQKV + 2048 + col);
        a = k[i]; dk[0] = __floats2half2_rn(a.x, a.y); dk[1] = __floats2half2_rn(a.z, a.w);
        __half2* dv = (__half2*)(d + (size_t)row * NQKV + 4096 + col);
        a = v[i]; dv[0] = __floats2half2_rn(a.x, a.y); dv[1] = __floats2half2_rn(a.z, a.w);
    }
}

// ---------------------------------------------------------------------------
// QR[i, r] = scale * (Q[i] . wk[r]).  wk cached in smem; Q fp16.
// ---------------------------------------------------------------------------
#define QR_BLOCKS 25
#define QR_ROWS   20
#define QR_THREADS (NREL * 32)  // 672
#define QR_SMEM ((NREL * DM + DM) * 4)

__global__ __launch_bounds__(QR_THREADS, 1) void qr_kernel(
    const __half* __restrict__ Q, int ldQ, const float* __restrict__ wk,
    float* __restrict__ QR, float scale)
{
    extern __shared__ float qsm[];
    float* wks = qsm;
    float* qv  = qsm + NREL * DM;
    const int tid = threadIdx.x, warp = tid / 32, lane = tid & 31;

    for (int t = tid; t < NREL * DM; t += QR_THREADS) wks[t] = wk[t];
    __syncthreads();

    for (int ii = 0; ii < QR_ROWS; ii++) {
        const int i = blockIdx.x * QR_ROWS + ii;
        for (int t = tid; t < DM; t += QR_THREADS)
            qv[t] = __half2float(Q[(size_t)i * ldQ + t]);
        __syncthreads();
        if (warp < NREL) {
            float s = 0.f;
            const float* wp = wks + warp * DM;
#pragma unroll 4
            for (int k = lane; k < DM; k += 32) s += qv[k] * wp[k];
#pragma unroll
            for (int o = 16; o > 0; o >>= 1) s += __shfl_xor_sync(0xffffffffu, s, o);
            if (lane == 0) QR[i * NREL + warp] = s * scale;
        }
        __syncthreads();
    }
}

// ---------------------------------------------------------------------------
// Fused: 8-way S-partial reduce + bias + mask + softmax.
// Writes fp32 Aout and fp16 A16 (zero-padded).
// ---------------------------------------------------------------------------
__global__ __launch_bounds__(512) void softmax_kernel(
    const float* __restrict__ SP, float* __restrict__ S,
    const float* __restrict__ QR, const int* __restrict__ mask,
    float* __restrict__ Aout, __half* __restrict__ A16, int n)
{
    const int i = blockIdx.x;
    __shared__ float red[512];
    const size_t CH = (size_t)NTOK * NTOK;
    float* row = S + (size_t)i * n;
    const int* mrow = mask + (size_t)i * n;
    float* arow = Aout + (size_t)i * n;
    __half* hrow = A16 + (size_t)i * NTOKP;

    float m = -INFINITY;
    for (int j = threadIdx.x; j < n; j += blockDim.x) {
        float v = 0.f;
        const size_t off = (size_t)i * n + j;
#pragma unroll
        for (int z = 0; z < SPL_S; z++) v += SP[z * CH + off];
        int d = j - i;
        d = min(max(d, -KWIN), KWIN);
        v += QR[i * NREL + d + KWIN];
        if (mrow[j] == 0) v = -1e9f;
        row[j] = v;
        m = fmaxf(m, v);
    }
    red[threadIdx.x] = m;
    __syncthreads();
    for (int s = 256; s > 0; s >>= 1) {
        if (threadIdx.x < s) red[threadIdx.x] = fmaxf(red[threadIdx.x], red[threadIdx.x + s]);
        __syncthreads();
    }
    m = red[0];
    __syncthreads();

    float sum = 0.f;
    for (int j = threadIdx.x; j < n; j += blockDim.x) {
        float e = expf(row[j] - m);
        row[j] = e;
        sum += e;
    }
    red[threadIdx.x] = sum;
    __syncthreads();
    for (int s = 256; s > 0; s >>= 1) {
        if (threadIdx.x < s) red[threadIdx.x] += red[threadIdx.x + s];
        __syncthreads();
    }
    const float inv = 1.0f / red[0];
    __syncthreads();

    for (int j = threadIdx.x; j < n; j += blockDim.x) {
        float a = row[j] * inv;
        arow[j] = a;
        hrow[j] = __float2half_rn(a);
    }
    for (int j = n + threadIdx.x; j < NTOKP; j += blockDim.x) hrow[j] = __float2half_rn(0.f);
}

// ---------------------------------------------------------------------------
extern "C" void kernel_launch(void* const* d_in, const int* in_sizes, int n_in,
                              void* d_out, int out_size)
{
    const float* X    = (const float*)d_in[0];
    const int*   mask = (const int*)  d_in[1];
    const float* Wq   = (const float*)d_in[2];
    const float* Wk   = (const float*)d_in[3];
    const float* Wv   = (const float*)d_in[4];
    const float* Wo   = (const float*)d_in[5];
    const float* wk   = (const float*)d_in[6];

    float* Y    = (float*)d_out;                 // [500, 2048]
    float* Aout = Y + (size_t)NTOK * DM;         // [500, 500]

    __half *X16, *W16, *Wo16, *QKV16, *A16, *T16;
    float *P, *S, *QR;
    cudaGetSymbolAddress((void**)&X16,   g_X16);
    cudaGetSymbolAddress((void**)&W16,   g_W16);
    cudaGetSymbolAddress((void**)&Wo16,  g_Wo16);
    cudaGetSymbolAddress((void**)&QKV16, g_QKV16);
    cudaGetSymbolAddress((void**)&A16,   g_A16);
    cudaGetSymbolAddress((void**)&T16,   g_T16);
    cudaGetSymbolAddress((void**)&P,     g_P);
    cudaGetSymbolAddress((void**)&S,     g_S);
    cudaGetSymbolAddress((void**)&QR,    g_QR);

    const int SM_1_4 = NSTAGE * (128 * SA * 2 + 64 * SB1 * 2);   // 107520
    const int SM_0_2 = NSTAGE * (64 * SA * 2 + 128 * SA * 2);    // 82944
    const int SM_1_2 = NSTAGE * (64 * SA * 2 + 64 * SB1 * 2);    // 79872
    cudaFuncSetAttribute((const void*)hgemm<1,4>, cudaFuncAttributeMaxDynamicSharedMemorySize, SM_1_4);
    cudaFuncSetAttribute((const void*)hgemm<0,2>, cudaFuncAttributeMaxDynamicSharedMemorySize, SM_0_2);
    cudaFuncSetAttribute((const void*)hgemm<1,2>, cudaFuncAttributeMaxDynamicSharedMemorySize, SM_1_2);
    cudaFuncSetAttribute((const void*)qr_kernel,  cudaFuncAttributeMaxDynamicSharedMemorySize, QR_SMEM);

    const float scale = 1.0f / sqrtf((float)DM);

    // 0) fp32 -> fp16 conversions
    cvt1<<<(NTOK * DM / 4 + 255) / 256, 256>>>((const float4*)X, (__half2*)X16, NTOK * DM / 4);
    cvt_fuse3<<<(DM * DM / 4 + 255) / 256, 256>>>(
        (const float4*)Wq, (const float4*)Wk, (const float4*)Wv, W16);
    cvt1<<<(DM * DM / 4 + 255) / 256, 256>>>((const float4*)Wo, (__half2*)Wo16, DM * DM / 4);

    const size_t CH_QKV = (size_t)NTOK * NQKV;   // 3.072M
    const size_t CH_S   = (size_t)NTOK * NTOK;   // 250K
    const size_t CH_TD  = (size_t)NTOK * DM;     // 1.024M

    // 1) QKV = X @ [Wq|Wk|Wv], split-K 2 -> partials, reduce to fp16
    hgemm<1,4><<<dim3(NQKV / 128, 4, 2), 256, SM_1_4>>>(
        X16, W16, P, NTOK, NQKV, 1024, DM, DM, NQKV, NQKV, CH_QKV, 1.0f);
    reduce2h<<<((int)CH_QKV / 4 + 255) / 256, 256>>>(P, CH_QKV, QKV16, (int)CH_QKV / 4);

    // 2) QR = scale * Q @ wk^T
    qr_kernel<<<QR_BLOCKS, QR_THREADS, QR_SMEM>>>(QKV16, NQKV, wk, QR, scale);

    // 3) S partials = scale * Q @ K^T, split-K 8 (reduced inside softmax)
    hgemm<0,2><<<dim3(4, 8, SPL_S), 256, SM_0_2>>>(
        QKV16, QKV16 + DM, P, NTOK, NTOK, 256, DM, NQKV, NQKV, NTOK, CH_S, scale);

    // 4) fused 8-way reduce + bias + mask + softmax
    softmax_kernel<<<NTOK, 512>>>(P, S, QR, mask, Aout, A16, NTOK);

    // 5) T = A @ V, split-K 2 (K padded to 512, V rows >=500 masked)
    hgemm<1,2><<<dim3(DM / 128, 8, 2), 256, SM_1_2>>>(
        A16, QKV16 + 2 * DM, P, NTOK, DM, 256, NTOK, NTOKP, NQKV, DM, CH_TD, 1.0f);
    reduce2h<<<((int)CH_TD / 4 + 255) / 256, 256>>>(P, CH_TD, T16, (int)CH_TD / 4);

    // 6) Y = T @ Wo, split-K 2 (fp32 out)
    hgemm<1,2><<<dim3(DM / 128, 8, 2), 256, SM_1_2>>>(
        T16, Wo16, P, NTOK, DM, 1024, DM, DM, DM, DM, CH_TD, 1.0f);
    reduce2f<<<((int)CH_TD / 4 + 255) / 256, 256>>>(P, CH_TD, Y, (int)CH_TD / 4);
}

// round 8
// speedup vs baseline: 11.1727x; 1.0361x over previous
#include <cuda_runtime.h>
#include <cuda_fp16.h>
#include <cstdint>
#include <math.h>

#define NTOK  500
#define NTOKP 512
#define DM    2048
#define KWIN  10
#define NREL  21
#define NQKV  6144
#define SPL_S 8

// ---------------- scratch (device globals; no allocation allowed) ----------
__device__ __align__(16) __half g_X16 [NTOK * DM];
__device__ __align__(16) __half g_W16 [DM * NQKV];     // [k][Wq|Wk|Wv]
__device__ __align__(16) __half g_Wo16[DM * DM];
__device__ __align__(16) __half g_QKV16[NTOK * NQKV];  // [tok][Q|K|V]
__device__ __align__(16) __half g_A16 [NTOK * NTOKP];  // attention, zero-padded cols
__device__ __align__(16) __half g_T16 [NTOK * DM];
__device__ __align__(16) float g_P [2 * NTOK * NQKV];  // split-K partials
__device__ float g_S [NTOK * NTOK];
__device__ float g_QR[NTOK * NREL];

// ---------------- PTX helpers ----------------------------------------------
__device__ __forceinline__ uint32_t smem_to_u32(const void* p) {
    uint32_t a;
    asm("{ .reg .u64 t; cvta.to.shared.u64 t, %1; cvt.u32.u64 %0, t; }" : "=r"(a) : "l"(p));
    return a;
}
__device__ __forceinline__ void cp16(uint32_t sa, const void* g, bool v) {
    asm volatile("cp.async.ca.shared.global [%0], [%1], 16, %2;"
                 :: "r"(sa), "l"(g), "r"(v ? 16u : 0u) : "memory");
}
__device__ __forceinline__ void ldsm4(uint32_t& r0, uint32_t& r1, uint32_t& r2, uint32_t& r3,
                                      uint32_t addr) {
    asm volatile("ldmatrix.sync.aligned.m8n8.x4.shared.b16 {%0,%1,%2,%3}, [%4];"
                 : "=r"(r0), "=r"(r1), "=r"(r2), "=r"(r3) : "r"(addr));
}
__device__ __forceinline__ void ldsm4t(uint32_t& r0, uint32_t& r1, uint32_t& r2, uint32_t& r3,
                                       uint32_t addr) {
    asm volatile("ldmatrix.sync.aligned.m8n8.x4.trans.shared.b16 {%0,%1,%2,%3}, [%4];"
                 : "=r"(r0), "=r"(r1), "=r"(r2), "=r"(r3) : "r"(addr));
}
__device__ __forceinline__ void mma16816(float* c, const uint32_t* a, uint32_t b0, uint32_t b1) {
    asm volatile("mma.sync.aligned.m16n8k16.row.col.f32.f16.f16.f32 "
                 "{%0,%1,%2,%3}, {%4,%5,%6,%7}, {%8,%9}, {%0,%1,%2,%3};"
                 : "+f"(c[0]), "+f"(c[1]), "+f"(c[2]), "+f"(c[3])
                 : "r"(a[0]), "r"(a[1]), "r"(a[2]), "r"(a[3]), "r"(b0), "r"(b1));
}

// ---------------------------------------------------------------------------
// Split-K fp16 GEMM, fp32 accumulate, fp32 partial output.
//   P[z] = alpha * A[M, kOff:kOff+kLen] @ op(B)
//   MODEB=0: B [N][K] row-major => A @ B^T   MODEB=1: B [K][N] row-major => A @ B
// CTA tile (MI*32) x 128, BK=64, 8 warps, 3-stage cp.async,
// 1 barrier/iter, loop-invariant load addressing (pointer bumps only).
// ---------------------------------------------------------------------------
#define BK 64
#define SA  72      // halves per row: 64 + 8 pad
#define SB1 136     // halves per row: 128 + 8 pad
#define NSTAGE 3

template<int MODEB, int MI>
__global__ __launch_bounds__(256, 2) void hgemm(
    const __half* __restrict__ A, const __half* __restrict__ B,
    float* __restrict__ P,
    int M, int N, int kLen, int KB,
    int ldA, int ldB, int ldC, size_t chunkStride, float alpha)
{
    constexpr int BM = MI * 32;
    constexpr int A_BYT = BM * SA * 2;
    constexpr int B_BYT = MODEB ? (64 * SB1 * 2) : (128 * SA * 2);
    constexpr int STG = A_BYT + B_BYT;
    constexpr int ACH = BM * 8 / 256;   // A 16B-chunks per thread
    constexpr int BCH = 4;              // B 16B-chunks per thread

    extern __shared__ char smem[];
    const uint32_t sb = smem_to_u32(smem);

    const int tid = threadIdx.x;
    const int lane = tid & 31, w = tid >> 5;
    const int wm = w & 1, wn = w >> 1;
    const int bm = blockIdx.y * BM, bn = blockIdx.x * 128;
    const int kOff = blockIdx.z * kLen;
    const int nIter = kLen / BK;
    float* Cp = P + (size_t)blockIdx.z * chunkStride;

    // ---- loop-invariant load state -------------------------------------
    const __half* pA[ACH];  bool vA[ACH];  uint32_t oA[ACH];
#pragma unroll
    for (int i = 0; i < ACH; i++) {
        int ch = tid + 256 * i;
        int r = ch >> 3, cb = ch & 7;
        pA[i] = A + (size_t)(bm + r) * ldA + kOff + cb * 8;
        vA[i] = (bm + r) < M;
        oA[i] = A_BYT * 0 + (r * SA + cb * 8) * 2;
    }
    const __half* pB[BCH];  bool vB[BCH];  int rB[BCH];  uint32_t oB[BCH];
#pragma unroll
    for (int i = 0; i < BCH; i++) {
        int ch = tid + 256 * i;
        if (MODEB) {
            int r = ch >> 4, cb = ch & 15;
            pB[i] = B + (size_t)(kOff + r) * ldB + bn + cb * 8;
            rB[i] = kOff + r;                  // current k for this chunk
            vB[i] = true;
            oB[i] = (r * SB1 + cb * 8) * 2;
        } else {
            int r = ch >> 3, cb = ch & 7;
            pB[i] = B + (size_t)(bn + r) * ldB + kOff + cb * 8;
            vB[i] = (bn + r) < N;
            rB[i] = 0;
            oB[i] = (r * SA + cb * 8) * 2;
        }
    }
    const size_t bStep = MODEB ? (size_t)BK * ldB : (size_t)BK;

    auto load = [&](int buf) {
        const uint32_t aS = sb + (uint32_t)buf * STG;
        const uint32_t bS = aS + A_BYT;
#pragma unroll
        for (int i = 0; i < ACH; i++) {
            cp16(aS + oA[i], pA[i], vA[i]);
            pA[i] += BK;
        }
#pragma unroll
        for (int i = 0; i < BCH; i++) {
            bool ok = MODEB ? (rB[i] < KB) : vB[i];
            cp16(bS + oB[i], pB[i], ok);
            pB[i] += bStep;
            if (MODEB) rB[i] += BK;
        }
        asm volatile("cp.async.commit_group;" ::: "memory");
    };

    float acc[MI][4][4];
#pragma unroll
    for (int i = 0; i < MI; i++)
#pragma unroll
        for (int j = 0; j < 4; j++)
#pragma unroll
            for (int t = 0; t < 4; t++) acc[i][j][t] = 0.f;

    load(0);
    load(1);

    const int arow  = lane & 15;
    const int acol  = (lane >> 4) * 8;
    const int b0row = (lane & 7) + ((lane >> 4) & 1) * 8;
    const int b0col = ((lane >> 3) & 1) * 8;
    const int b1row = (lane & 7) + ((lane >> 3) & 1) * 8;
    const int b1col = ((lane >> 4) & 1) * 8;

    for (int it = 0; it < nIter; ++it) {
        asm volatile("cp.async.wait_group 1;" ::: "memory");
        __syncthreads();

        const uint32_t aS = sb + (uint32_t)(it % NSTAGE) * STG;
        const uint32_t bS = aS + A_BYT;

#pragma unroll
        for (int kk = 0; kk < 4; kk++) {
            uint32_t a[MI][4];
#pragma unroll
            for (int mi = 0; mi < MI; mi++) {
                uint32_t addr = aS + (uint32_t)((((wm * MI + mi) * 16 + arow) * SA) + kk * 16 + acol) * 2;
                ldsm4(a[mi][0], a[mi][1], a[mi][2], a[mi][3], addr);
            }
            uint32_t b[2][4];
#pragma unroll
            for (int nb = 0; nb < 2; nb++) {
                if (MODEB) {
                    uint32_t addr = bS + (uint32_t)(((kk * 16 + b1row) * SB1) + wn * 32 + nb * 16 + b1col) * 2;
                    ldsm4t(b[nb][0], b[nb][1], b[nb][2], b[nb][3], addr);
                } else {
                    uint32_t addr = bS + (uint32_t)(((wn * 32 + nb * 16 + b0row) * SA) + kk * 16 + b0col) * 2;
                    ldsm4(b[nb][0], b[nb][1], b[nb][2], b[nb][3], addr);
                }
            }
#pragma unroll
            for (int mi = 0; mi < MI; mi++)
#pragma unroll
                for (int nj = 0; nj < 4; nj++)
                    mma16816(acc[mi][nj], a[mi],
                             b[nj >> 1][2 * (nj & 1)], b[nj >> 1][2 * (nj & 1) + 1]);

            // overlap next-stage load issue with kk=1..3 compute
            if (kk == 0) {
                if (it + 2 < nIter) load((it + 2) % NSTAGE);
                else asm volatile("cp.async.commit_group;" ::: "memory");
            }
        }
        // no bottom barrier: next iteration's top barrier orders buffer reuse
    }

    // ---- epilogue: fp32 partials -----------------------------------------
#pragma unroll
    for (int mi = 0; mi < MI; mi++) {
        const int r0 = bm + (wm * MI + mi) * 16 + (lane >> 2);
#pragma unroll
        for (int nj = 0; nj < 4; nj++) {
            const int c0 = bn + wn * 32 + nj * 8 + 2 * (lane & 3);
            const float* ac = acc[mi][nj];
            if (r0 < M && c0 < N)
                *(float2*)(Cp + (size_t)r0 * ldC + c0) =
                    make_float2(ac[0] * alpha, ac[1] * alpha);
            if (r0 + 8 < M && c0 < N)
                *(float2*)(Cp + (size_t)(r0 + 8) * ldC + c0) =
                    make_float2(ac[2] * alpha, ac[3] * alpha);
        }
    }
}

// ---------------------------------------------------------------------------
// Reductions of 2-way split-K partials (deterministic, no atomics)
// ---------------------------------------------------------------------------
__global__ void reduce2h(const float* __restrict__ P, size_t CH,
                         __half* __restrict__ out, int n4) {
    int i = blockIdx.x * blockDim.x + threadIdx.x;
    if (i < n4) {
        float4 a = *(const float4*)(P + 4 * (size_t)i);
        float4 b = *(const float4*)(P + CH + 4 * (size_t)i);
        __half2* o = (__half2*)(out + 4 * (size_t)i);
        o[0] = __floats2half2_rn(a.x + b.x, a.y + b.y);
        o[1] = __floats2half2_rn(a.z + b.z, a.w + b.w);
    }
}
__global__ void reduce2f(const float* __restrict__ P, size_t CH,
                         float* __restrict__ out, int n4) {
    int i = blockIdx.x * blockDim.x + threadIdx.x;
    if (i < n4) {
        float4 a = *(const float4*)(P + 4 * (size_t)i);
        float4 b = *(const float4*)(P + CH + 4 * (size_t)i);
        *(float4*)(out + 4 * (size_t)i) =
            make_float4(a.x + b.x, a.y + b.y, a.z + b.z, a.w + b.w);
    }
}

// ---------------------------------------------------------------------------
// fp32 -> fp16 conversion kernels
// ---------------------------------------------------------------------------
__global__ void cvt1(const float4* __restrict__ s, __half2* __restrict__ d, int n4) {
    int i = blockIdx.x * blockDim.x + threadIdx.x;
    if (i < n4) {
        float4 v = s[i];
        d[2 * i]     = __floats2half2_rn(v.x, v.y);
        d[2 * i + 1] = __floats2half2_rn(v.z, v.w);
    }
}
__global__ void cvt_fuse3(const float4* __restrict__ q, const float4* __restrict__ k,
                          const float4* __restrict__ v, __half* __restrict__ d) {
    int i = blockIdx.x * blockDim.x + threadIdx.x;
    if (i < DM * DM / 4) {
        int p = i * 4;
        int row = p >> 11, col = p & 2047;
        float4 a;
        __half2* dq = (__half2*)(d + (size_t)row * NQKV + col);
        a = q[i]; dq[0] = __floats2half2_rn(a.x, a.y); dq[1] = __floats2half2_rn(a.z, a.w);
        __half2* dk = (__half2*)(d + (size_t)row * NQKV + 2048 + col);
        a = k[i]; dk[0] = __floats2half2_rn(a.x, a.y); dk[1] = __floats2half2_rn(a.z, a.w);
        __half2* dv = (__half2*)(d + (size_t)row * NQKV + 4096 + col);
        a = v[i]; dv[0] = __floats2half2_rn(a.x, a.y); dv[1] = __floats2half2_rn(a.z, a.w);
    }
}

// ---------------------------------------------------------------------------
// QR[i, r] = scale * (Q[i] . wk[r]).  wk cached in smem; Q fp16.
// ---------------------------------------------------------------------------
#define QR_BLOCKS 25
#define QR_ROWS   20
#define QR_THREADS (NREL * 32)  // 672
#define QR_SMEM ((NREL * DM + DM) * 4)

__global__ __launch_bounds__(QR_THREADS, 1) void qr_kernel(
    const __half* __restrict__ Q, int ldQ, const float* __restrict__ wk,
    float* __restrict__ QR, float scale)
{
    extern __shared__ float qsm[];
    float* wks = qsm;
    float* qv  = qsm + NREL * DM;
    const int tid = threadIdx.x, warp = tid / 32, lane = tid & 31;

    for (int t = tid; t < NREL * DM; t += QR_THREADS) wks[t] = wk[t];
    __syncthreads();

    for (int ii = 0; ii < QR_ROWS; ii++) {
        const int i = blockIdx.x * QR_ROWS + ii;
        for (int t = tid; t < DM; t += QR_THREADS)
            qv[t] = __half2float(Q[(size_t)i * ldQ + t]);
        __syncthreads();
        if (warp < NREL) {
            float s = 0.f;
            const float* wp = wks + warp * DM;
#pragma unroll 4
            for (int k = lane; k < DM; k += 32) s += qv[k] * wp[k];
#pragma unroll
            for (int o = 16; o > 0; o >>= 1) s += __shfl_xor_sync(0xffffffffu, s, o);
            if (lane == 0) QR[i * NREL + warp] = s * scale;
        }
        __syncthreads();
    }
}

// ---------------------------------------------------------------------------
// Fused: 8-way S-partial reduce + bias + mask + softmax.
// ---------------------------------------------------------------------------
__global__ __launch_bounds__(512) void softmax_kernel(
    const float* __restrict__ SP, float* __restrict__ S,
    const float* __restrict__ QR, const int* __restrict__ mask,
    float* __restrict__ Aout, __half* __restrict__ A16, int n)
{
    const int i = blockIdx.x;
    __shared__ float red[512];
    const size_t CH = (size_t)NTOK * NTOK;
    float* row = S + (size_t)i * n;
    const int* mrow = mask + (size_t)i * n;
    float* arow = Aout + (size_t)i * n;
    __half* hrow = A16 + (size_t)i * NTOKP;

    float m = -INFINITY;
    for (int j = threadIdx.x; j < n; j += blockDim.x) {
        float v = 0.f;
        const size_t off = (size_t)i * n + j;
#pragma unroll
        for (int z = 0; z < SPL_S; z++) v += SP[z * CH + off];
        int d = j - i;
        d = min(max(d, -KWIN), KWIN);
        v += QR[i * NREL + d + KWIN];
        if (mrow[j] == 0) v = -1e9f;
        row[j] = v;
        m = fmaxf(m, v);
    }
    red[threadIdx.x] = m;
    __syncthreads();
    for (int s = 256; s > 0; s >>= 1) {
        if (threadIdx.x < s) red[threadIdx.x] = fmaxf(red[threadIdx.x], red[threadIdx.x + s]);
        __syncthreads();
    }
    m = red[0];
    __syncthreads();

    float sum = 0.f;
    for (int j = threadIdx.x; j < n; j += blockDim.x) {
        float e = expf(row[j] - m);
        row[j] = e;
        sum += e;
    }
    red[threadIdx.x] = sum;
    __syncthreads();
    for (int s = 256; s > 0; s >>= 1) {
        if (threadIdx.x < s) red[threadIdx.x] += red[threadIdx.x + s];
        __syncthreads();
    }
    const float inv = 1.0f / red[0];
    __syncthreads();

    for (int j = threadIdx.x; j < n; j += blockDim.x) {
        float a = row[j] * inv;
        arow[j] = a;
        hrow[j] = __float2half_rn(a);
    }
    for (int j = n + threadIdx.x; j < NTOKP; j += blockDim.x) hrow[j] = __float2half_rn(0.f);
}

// ---------------------------------------------------------------------------
extern "C" void kernel_launch(void* const* d_in, const int* in_sizes, int n_in,
                              void* d_out, int out_size)
{
    const float* X    = (const float*)d_in[0];
    const int*   mask = (const int*)  d_in[1];
    const float* Wq   = (const float*)d_in[2];
    const float* Wk   = (const float*)d_in[3];
    const float* Wv   = (const float*)d_in[4];
    const float* Wo   = (const float*)d_in[5];
    const float* wk   = (const float*)d_in[6];

    float* Y    = (float*)d_out;                 // [500, 2048]
    float* Aout = Y + (size_t)NTOK * DM;         // [500, 500]

    __half *X16, *W16, *Wo16, *QKV16, *A16, *T16;
    float *P, *S, *QR;
    cudaGetSymbolAddress((void**)&X16,   g_X16);
    cudaGetSymbolAddress((void**)&W16,   g_W16);
    cudaGetSymbolAddress((void**)&Wo16,  g_Wo16);
    cudaGetSymbolAddress((void**)&QKV16, g_QKV16);
    cudaGetSymbolAddress((void**)&A16,   g_A16);
    cudaGetSymbolAddress((void**)&T16,   g_T16);
    cudaGetSymbolAddress((void**)&P,     g_P);
    cudaGetSymbolAddress((void**)&S,     g_S);
    cudaGetSymbolAddress((void**)&QR,    g_QR);

    const int SM_1_4 = NSTAGE * (128 * SA * 2 + 64 * SB1 * 2);   // 107520
    const int SM_0_2 = NSTAGE * (64 * SA * 2 + 128 * SA * 2);    // 82944
    const int SM_1_2 = NSTAGE * (64 * SA * 2 + 64 * SB1 * 2);    // 79872
    cudaFuncSetAttribute((const void*)hgemm<1,4>, cudaFuncAttributeMaxDynamicSharedMemorySize, SM_1_4);
    cudaFuncSetAttribute((const void*)hgemm<0,2>, cudaFuncAttributeMaxDynamicSharedMemorySize, SM_0_2);
    cudaFuncSetAttribute((const void*)hgemm<1,2>, cudaFuncAttributeMaxDynamicSharedMemorySize, SM_1_2);
    cudaFuncSetAttribute((const void*)qr_kernel,  cudaFuncAttributeMaxDynamicSharedMemorySize, QR_SMEM);

    const float scale = 1.0f / sqrtf((float)DM);

    // 0) fp32 -> fp16 conversions
    cvt1<<<(NTOK * DM / 4 + 255) / 256, 256>>>((const float4*)X, (__half2*)X16, NTOK * DM / 4);
    cvt_fuse3<<<(DM * DM / 4 + 255) / 256, 256>>>(
        (const float4*)Wq, (const float4*)Wk, (const float4*)Wv, W16);
    cvt1<<<(DM * DM / 4 + 255) / 256, 256>>>((const float4*)Wo, (__half2*)Wo16, DM * DM / 4);

    const size_t CH_QKV = (size_t)NTOK * NQKV;
    const size_t CH_S   = (size_t)NTOK * NTOK;
    const size_t CH_TD  = (size_t)NTOK * DM;

    // 1) QKV = X @ [Wq|Wk|Wv], split-K 2 -> partials, reduce to fp16
    hgemm<1,4><<<dim3(NQKV / 128, 4, 2), 256, SM_1_4>>>(
        X16, W16, P, NTOK, NQKV, 1024, DM, DM, NQKV, NQKV, CH_QKV, 1.0f);
    reduce2h<<<((int)CH_QKV / 4 + 255) / 256, 256>>>(P, CH_QKV, QKV16, (int)CH_QKV / 4);

    // 2) QR = scale * Q @ wk^T
    qr_kernel<<<QR_BLOCKS, QR_THREADS, QR_SMEM>>>(QKV16, NQKV, wk, QR, scale);

    // 3) S partials = scale * Q @ K^T, split-K 8 (reduced inside softmax)
    hgemm<0,2><<<dim3(4, 8, SPL_S), 256, SM_0_2>>>(
        QKV16, QKV16 + DM, P, NTOK, NTOK, 256, DM, NQKV, NQKV, NTOK, CH_S, scale);

    // 4) fused 8-way reduce + bias + mask + softmax
    softmax_kernel<<<NTOK, 512>>>(P, S, QR, mask, Aout, A16, NTOK);

    // 5) T = A @ V, split-K 2 (K padded to 512, V rows >=500 masked)
    hgemm<1,2><<<dim3(DM / 128, 8, 2), 256, SM_1_2>>>(
        A16, QKV16 + 2 * DM, P, NTOK, DM, 256, NTOK, NTOKP, NQKV, DM, CH_TD, 1.0f);
    reduce2h<<<((int)CH_TD / 4 + 255) / 256, 256>>>(P, CH_TD, T16, (int)CH_TD / 4);

    // 6) Y = T @ Wo, split-K 2 (fp32 out)
    hgemm<1,2><<<dim3(DM / 128, 8, 2), 256, SM_1_2>>>(
        T16, Wo16, P, NTOK, DM, 1024, DM, DM, DM, DM, CH_TD, 1.0f);
    reduce2f<<<((int)CH_TD / 4 + 255) / 256, 256>>>(P, CH_TD, Y, (int)CH_TD / 4);
}